// round 3
// baseline (speedup 1.0000x reference)
#include <cuda_runtime.h>
#include <cuda_bf16.h>

// ---------------- scratch (device globals; no allocations allowed) ----------
__device__ float g_qkv[1024 * 3072];   // QKV projection output [N][3D]
__device__ float g_ctx[1024 * 1024];   // attention context     [N][D]

// ---------------- tiled fp32 GEMM:  C[M,N] = A[M,K] @ B[N,K]^T + bias[N] ----
// 128x128 block tile, BK=16, 256 threads, 8x8 register tile per thread.
__global__ __launch_bounds__(256) void gemm_bias_128(
    const float* __restrict__ A, const float* __restrict__ B,
    const float* __restrict__ bias, float* __restrict__ C,
    int M, int N, int K)
{
    __shared__ float As[16][132];   // stored transposed: As[k][m]
    __shared__ float Bs[16][132];   // stored transposed: Bs[k][n]

    const int tid = threadIdx.x;
    const int tx = tid & 15;        // 16 col groups
    const int ty = tid >> 4;        // 16 row groups
    const int bm = blockIdx.y;
    const int bn = blockIdx.x;

    const float* Ab = A + (size_t)bm * 128 * K;
    const float* Bb = B + (size_t)bn * 128 * K;

    float acc[8][8];
#pragma unroll
    for (int i = 0; i < 8; i++)
#pragma unroll
        for (int j = 0; j < 8; j++) acc[i][j] = 0.0f;

    for (int k0 = 0; k0 < K; k0 += 16) {
        // load 128x16 tiles of A and B (float4 along K), store transposed
#pragma unroll
        for (int u = 0; u < 2; u++) {
            int f4  = tid * 2 + u;          // 0..511
            int row = f4 >> 2;              // 0..127
            int c4  = (f4 & 3) * 4;         // 0,4,8,12
            float4 av = *(const float4*)(Ab + (size_t)row * K + k0 + c4);
            As[c4 + 0][row] = av.x;
            As[c4 + 1][row] = av.y;
            As[c4 + 2][row] = av.z;
            As[c4 + 3][row] = av.w;
            float4 bv = *(const float4*)(Bb + (size_t)row * K + k0 + c4);
            Bs[c4 + 0][row] = bv.x;
            Bs[c4 + 1][row] = bv.y;
            Bs[c4 + 2][row] = bv.z;
            Bs[c4 + 3][row] = bv.w;
        }
        __syncthreads();

#pragma unroll
        for (int kk = 0; kk < 16; kk++) {
            float a[8], b[8];
            *(float4*)(a + 0) = *(const float4*)&As[kk][ty * 8 + 0];
            *(float4*)(a + 4) = *(const float4*)&As[kk][ty * 8 + 4];
            *(float4*)(b + 0) = *(const float4*)&Bs[kk][tx * 8 + 0];
            *(float4*)(b + 4) = *(const float4*)&Bs[kk][tx * 8 + 4];
#pragma unroll
            for (int i = 0; i < 8; i++)
#pragma unroll
                for (int j = 0; j < 8; j++)
                    acc[i][j] += a[i] * b[j];
        }
        __syncthreads();
    }

    // epilogue: add bias, write C
#pragma unroll
    for (int i = 0; i < 8; i++) {
        int row = bm * 128 + ty * 8 + i;
        float* Cp = C + (size_t)row * N + bn * 128 + tx * 8;
#pragma unroll
        for (int j = 0; j < 8; j++)
            acc[i][j] += __ldg(&bias[bn * 128 + tx * 8 + j]);
        *(float4*)(Cp + 0) = make_float4(acc[i][0], acc[i][1], acc[i][2], acc[i][3]);
        *(float4*)(Cp + 4) = make_float4(acc[i][4], acc[i][5], acc[i][6], acc[i][7]);
    }
}

// ---------------- fused window attention (flash-style, online softmax) ------
// Grid: (16 q-blocks, 16 heads), 256 threads. Tile: 64 q-rows x 64 kv-cols.
// Thread (ty 0..15, tx 0..15) owns a 4x4 s-tile: rows ty*4+qi, cols tx*4+ci.
// Relative-position bias: idx = min(63*((qsum - msum) + 62), 3968)  (JAX clamp).
#define ATTN_SMEM_FLOATS (64*68 /*q*/ + 64*64 /*k*/ + 64*68 /*v*/ + 64*68 /*p*/ + 64 /*msum*/)
#define ATTN_SMEM_BYTES  (ATTN_SMEM_FLOATS * 4)

__global__ __launch_bounds__(256) void attn_kernel(
    const float* __restrict__ qkv, const float* __restrict__ bias_table,
    float* __restrict__ ctx)
{
    extern __shared__ float sm[];
    float* q_s   = sm;                 // [64][68]  natural layout
    float* k_s   = q_s + 64 * 68;      // [64][64]  16B-chunk swizzled
    float* v_s   = k_s + 64 * 64;      // [64][68]  natural layout
    float* p_s   = v_s + 64 * 68;      // [64][68]
    int*  msum_s = (int*)(p_s + 64 * 68); // [64]

    const int tid = threadIdx.x;
    const int tx  = tid & 15;
    const int ty  = tid >> 4;
    const int h   = blockIdx.y;
    const int qb  = blockIdx.x;
    const int n0  = qb * 64;
    const int qoff = h * 64;
    const int koff = 1024 + h * 64;
    const int voff = 2048 + h * 64;

    // load q block, pre-scaled by dh^-0.5 = 0.125
    for (int idx = tid; idx < 1024; idx += 256) {
        int row = idx >> 4;
        int c4  = (idx & 15) * 4;
        float4 v = *(const float4*)(qkv + (size_t)(n0 + row) * 3072 + qoff + c4);
        v.x *= 0.125f; v.y *= 0.125f; v.z *= 0.125f; v.w *= 0.125f;
        *(float4*)&q_s[row * 68 + c4] = v;
    }

    int qsum[4];
#pragma unroll
    for (int qi = 0; qi < 4; qi++) {
        int n = n0 + ty * 4 + qi;
        qsum[qi] = (n >> 5) + (n & 31);
    }

    float mrow[4], lrow[4], o[4][4];
#pragma unroll
    for (int qi = 0; qi < 4; qi++) {
        mrow[qi] = -1e30f;
        lrow[qi] = 0.0f;
#pragma unroll
        for (int j = 0; j < 4; j++) o[qi][j] = 0.0f;
    }

    for (int kv = 0; kv < 16; kv++) {
        __syncthreads();   // prior o-accum done reading v_s/p_s (and q_s ready on iter 0)
        const int m0 = kv * 64;
        for (int idx = tid; idx < 1024; idx += 256) {
            int row = idx >> 4;        // kv col c
            int d4  = idx & 15;        // logical 16B chunk along d
            float4 kvv = *(const float4*)(qkv + (size_t)(m0 + row) * 3072 + koff + d4 * 4);
            int dsw = d4 ^ ((row >> 2) & 7);     // swizzle for conflict-free reads
            *(float4*)&k_s[row * 64 + dsw * 4] = kvv;
            float4 vv = *(const float4*)(qkv + (size_t)(m0 + row) * 3072 + voff + d4 * 4);
            *(float4*)&v_s[row * 68 + d4 * 4] = vv;
        }
        if (tid < 64) {
            int m = m0 + tid;
            msum_s[tid] = (m >> 5) + (m & 31);
        }
        __syncthreads();

        // ---- s = q . k^T  (4x4 per thread) ----
        float s[4][4];
#pragma unroll
        for (int qi = 0; qi < 4; qi++)
#pragma unroll
            for (int ci = 0; ci < 4; ci++) s[qi][ci] = 0.0f;

#pragma unroll
        for (int d4 = 0; d4 < 16; d4++) {
            float4 q4[4];
#pragma unroll
            for (int qi = 0; qi < 4; qi++)
                q4[qi] = *(const float4*)&q_s[(ty * 4 + qi) * 68 + d4 * 4];
#pragma unroll
            for (int ci = 0; ci < 4; ci++) {
                int c = tx * 4 + ci;
                float4 k4 = *(const float4*)&k_s[c * 64 + (d4 ^ ((c >> 2) & 7)) * 4];
#pragma unroll
                for (int qi = 0; qi < 4; qi++) {
                    s[qi][ci] += q4[qi].x * k4.x;
                    s[qi][ci] += q4[qi].y * k4.y;
                    s[qi][ci] += q4[qi].z * k4.z;
                    s[qi][ci] += q4[qi].w * k4.w;
                }
            }
        }

        // ---- bias + online softmax + stage p through smem ----
#pragma unroll
        for (int qi = 0; qi < 4; qi++) {
            float mx = -1e30f;
#pragma unroll
            for (int ci = 0; ci < 4; ci++) {
                int c = tx * 4 + ci;
                int bidx = 63 * (qsum[qi] - msum_s[c] + 62);
                bidx = min(bidx, 3968);                      // JAX gather clamps OOB
                s[qi][ci] += __ldg(&bias_table[bidx * 16 + h]);
                mx = fmaxf(mx, s[qi][ci]);
            }
            mx = fmaxf(mx, __shfl_xor_sync(0xffffffffu, mx, 1));
            mx = fmaxf(mx, __shfl_xor_sync(0xffffffffu, mx, 2));
            mx = fmaxf(mx, __shfl_xor_sync(0xffffffffu, mx, 4));
            mx = fmaxf(mx, __shfl_xor_sync(0xffffffffu, mx, 8));
            float newm = fmaxf(mrow[qi], mx);
            float corr = __expf(mrow[qi] - newm);
            float p0 = __expf(s[qi][0] - newm);
            float p1 = __expf(s[qi][1] - newm);
            float p2 = __expf(s[qi][2] - newm);
            float p3 = __expf(s[qi][3] - newm);
            float ps = p0 + p1 + p2 + p3;
            ps += __shfl_xor_sync(0xffffffffu, ps, 1);
            ps += __shfl_xor_sync(0xffffffffu, ps, 2);
            ps += __shfl_xor_sync(0xffffffffu, ps, 4);
            ps += __shfl_xor_sync(0xffffffffu, ps, 8);
            lrow[qi] = lrow[qi] * corr + ps;
            mrow[qi] = newm;
#pragma unroll
            for (int j = 0; j < 4; j++) o[qi][j] *= corr;
            *(float4*)&p_s[(ty * 4 + qi) * 68 + tx * 4] = make_float4(p0, p1, p2, p3);
        }
        __syncthreads();

        // ---- o += p @ v  (thread owns dims dd = tx*4..tx*4+3) ----
#pragma unroll
        for (int c4 = 0; c4 < 16; c4++) {
            float p4[4][4];
#pragma unroll
            for (int qi = 0; qi < 4; qi++)
                *(float4*)p4[qi] = *(const float4*)&p_s[(ty * 4 + qi) * 68 + c4 * 4];
#pragma unroll
            for (int cc = 0; cc < 4; cc++) {
                float4 v4 = *(const float4*)&v_s[(c4 * 4 + cc) * 68 + tx * 4];
#pragma unroll
                for (int qi = 0; qi < 4; qi++) {
                    float pv = p4[qi][cc];
                    o[qi][0] += pv * v4.x;
                    o[qi][1] += pv * v4.y;
                    o[qi][2] += pv * v4.z;
                    o[qi][3] += pv * v4.w;
                }
            }
        }
    }

    // ---- normalize and write context [n][h*64 + dd] ----
#pragma unroll
    for (int qi = 0; qi < 4; qi++) {
        float inv = 1.0f / lrow[qi];
        float4 r = make_float4(o[qi][0] * inv, o[qi][1] * inv,
                               o[qi][2] * inv, o[qi][3] * inv);
        *(float4*)(ctx + (size_t)(n0 + ty * 4 + qi) * 1024 + h * 64 + tx * 4) = r;
    }
}

// ---------------- launch -----------------------------------------------------
extern "C" void kernel_launch(void* const* d_in, const int* in_sizes, int n_in,
                              void* d_out, int out_size)
{
    const float* x          = (const float*)d_in[0];   // [1024,1024]
    const float* w_qkv      = (const float*)d_in[1];   // [3072,1024]
    const float* b_qkv      = (const float*)d_in[2];   // [3072]
    const float* w_proj     = (const float*)d_in[3];   // [1024,1024]
    const float* b_proj     = (const float*)d_in[4];   // [1024]
    const float* bias_table = (const float*)d_in[5];   // [3969,16]
    float* out = (float*)d_out;                        // [1024,1024]

    (void)in_sizes; (void)n_in; (void)out_size;

    cudaFuncSetAttribute(attn_kernel,
                         cudaFuncAttributeMaxDynamicSharedMemorySize,
                         ATTN_SMEM_BYTES);

    float* qkv;
    float* ctx;
    cudaGetSymbolAddress((void**)&qkv, g_qkv);
    cudaGetSymbolAddress((void**)&ctx, g_ctx);

    // 1) QKV projection: [1024,3072] = x @ w_qkv^T + b_qkv
    gemm_bias_128<<<dim3(3072 / 128, 1024 / 128), 256>>>(
        x, w_qkv, b_qkv, qkv, 1024, 3072, 1024);

    // 2) fused window attention with relative-position bias
    attn_kernel<<<dim3(16, 16), 256, ATTN_SMEM_BYTES>>>(qkv, bias_table, ctx);

    // 3) output projection: out = ctx @ w_proj^T + b_proj
    gemm_bias_128<<<dim3(1024 / 128, 1024 / 128), 256>>>(
        ctx, w_proj, b_proj, out, 1024, 1024, 1024);
}

// round 5
// speedup vs baseline: 1.9027x; 1.9027x over previous
#include <cuda_runtime.h>
#include <cuda_bf16.h>
#include <cstdint>

// ---------------- scratch (device globals; no allocations allowed) ----------
__device__ float g_qkv[1024 * 3072];           // QKV projection output [N][3D]
__device__ float g_ctx[1024 * 1024];           // attention context     [N][D]
__device__ __nv_bfloat16 g_x0[1024 * 1024],    g_x1[1024 * 1024];     // x planes
__device__ __nv_bfloat16 g_wqkv0[3072 * 1024], g_wqkv1[3072 * 1024]; // w_qkv planes
__device__ __nv_bfloat16 g_wp0[1024 * 1024],   g_wp1[1024 * 1024];   // w_proj planes
__device__ __nv_bfloat16 g_c0[1024 * 1024],    g_c1[1024 * 1024];    // ctx planes

// ---------------- helpers ----------------------------------------------------
__device__ __forceinline__ uint32_t smem_u32(const void* p) {
    uint32_t a;
    asm("{ .reg .u64 t; cvta.to.shared.u64 t, %1; cvt.u32.u64 %0, t; }" : "=r"(a) : "l"(p));
    return a;
}
#define SMEM_SWIZZLE_128B(b) ((b) ^ (((b) >> 3) & 0x70))

__device__ __forceinline__ void cp_async16(uint32_t dst, const void* src) {
    asm volatile("cp.async.cg.shared.global [%0], [%1], 16;" :: "r"(dst), "l"(src) : "memory");
}
__device__ __forceinline__ void ldsm4(uint32_t& r0, uint32_t& r1, uint32_t& r2,
                                      uint32_t& r3, uint32_t addr) {
    asm volatile("ldmatrix.sync.aligned.m8n8.x4.shared.b16 {%0,%1,%2,%3}, [%4];"
                 : "=r"(r0), "=r"(r1), "=r"(r2), "=r"(r3) : "r"(addr));
}
// d += A(16x16 bf16) * B(16x8 bf16), fp32 accum. A row-major frag, B col-major frag.
__device__ __forceinline__ void mma16816(float* d, const uint32_t* a, const uint32_t* b) {
    asm volatile(
        "mma.sync.aligned.m16n8k16.row.col.f32.bf16.bf16.f32 "
        "{%0,%1,%2,%3}, {%4,%5,%6,%7}, {%8,%9}, {%0,%1,%2,%3};"
        : "+f"(d[0]), "+f"(d[1]), "+f"(d[2]), "+f"(d[3])
        : "r"(a[0]), "r"(a[1]), "r"(a[2]), "r"(a[3]), "r"(b[0]), "r"(b[1]));
}

// ---------------- split fp32 -> (bf16 hi, bf16 lo) ---------------------------
__global__ __launch_bounds__(256) void split_kernel(
    const float* __restrict__ src, __nv_bfloat16* __restrict__ p0,
    __nv_bfloat16* __restrict__ p1, int n)
{
    int i = (blockIdx.x * 256 + threadIdx.x) * 4;
    if (i >= n) return;
    float4 v = *(const float4*)(src + i);
    float vv[4] = {v.x, v.y, v.z, v.w};
    __nv_bfloat16 h0[4], h1[4];
#pragma unroll
    for (int j = 0; j < 4; j++) {
        h0[j] = __float2bfloat16_rn(vv[j]);
        h1[j] = __float2bfloat16_rn(vv[j] - __bfloat162float(h0[j]));
    }
    *(uint2*)(p0 + i) = *(const uint2*)h0;
    *(uint2*)(p1 + i) = *(const uint2*)h1;
}

// ---------------- mma.sync GEMM: C[M,N] = A@B^T + bias, bf16 split-2 --------
// Block tile 128x128, K-chunk 64, double-buffered smem {a0,a1,b0,b1} 16KB each.
// 8 warps: warp (wm 0..1, wn 0..3) owns a 64x32 tile = 4x4 m16n8 frags.
// 3 mma passes per k-step (a0b0, a0b1, a1b0) share one fp32 accumulator.
#define GEMM_SMEM_BYTES (2 * 4 * 16384)

__global__ __launch_bounds__(256, 1) void mma_gemm(
    const __nv_bfloat16* __restrict__ A0, const __nv_bfloat16* __restrict__ A1,
    const __nv_bfloat16* __restrict__ B0, const __nv_bfloat16* __restrict__ B1,
    const float* __restrict__ bias, float* __restrict__ C, int N, int K)
{
    extern __shared__ char smem[];
    const uint32_t sb = smem_u32(smem);
    const int tid  = threadIdx.x;
    const int lane = tid & 31;
    const int wid  = tid >> 5;
    const int wm   = wid >> 2;          // 0..1  (m offset wm*64)
    const int wn   = wid & 3;           // 0..3  (n offset wn*32)
    const int bm = blockIdx.y, bn = blockIdx.x;

    const __nv_bfloat16* planes[4];
    planes[0] = A0 + (size_t)bm * 128 * K;
    planes[1] = A1 + (size_t)bm * 128 * K;
    planes[2] = B0 + (size_t)bn * 128 * K;
    planes[3] = B1 + (size_t)bn * 128 * K;

    float acc[4][4][4];                 // [mt][nt][frag]
#pragma unroll
    for (int i = 0; i < 4; i++)
#pragma unroll
        for (int j = 0; j < 4; j++)
#pragma unroll
            for (int q = 0; q < 4; q++) acc[i][j][q] = 0.0f;

    const int NCHUNK = K / 64;

    // precomputed ldmatrix address components (within-tile)
    const int a_row  = lane & 15;             // row within 16-row m-tile
    const int a_kofs = (lane >> 4) * 8;       // 0 or 8 (k within 16)
    const int b_n    = ((lane >> 4) << 3) + (lane & 7);  // n within 16
    const int b_kofs = lane & 8;              // 0 or 8

    // chunk loader: 4 tiles x 1024 uint4
    auto load_chunk = [&](int c) {
        const uint32_t bb = sb + (uint32_t)(c & 1) * 65536;
        const int k0 = c * 64;
#pragma unroll
        for (int i = 0; i < 16; i++) {
            int idx  = i * 256 + tid;
            int tile = idx >> 10;
            int w    = idx & 1023;
            int row  = w >> 3;
            int j    = w & 7;
            uint32_t boff = (uint32_t)(row * 128 + j * 16);
            cp_async16(bb + tile * 16384 + SMEM_SWIZZLE_128B(boff),
                       planes[tile] + (size_t)row * K + k0 + j * 8);
        }
        asm volatile("cp.async.commit_group;" ::: "memory");
    };

    load_chunk(0);

    for (int c = 0; c < NCHUNK; c++) {
        if (c + 1 < NCHUNK) {
            load_chunk(c + 1);
            asm volatile("cp.async.wait_group 1;" ::: "memory");
        } else {
            asm volatile("cp.async.wait_group 0;" ::: "memory");
        }
        __syncthreads();

        const uint32_t bb = sb + (uint32_t)(c & 1) * 65536;
#pragma unroll
        for (int ks = 0; ks < 4; ks++) {
            // A fragments: [plane][mt][4]
            uint32_t af[2][4][4];
#pragma unroll
            for (int pl = 0; pl < 2; pl++)
#pragma unroll
                for (int mt = 0; mt < 4; mt++) {
                    uint32_t boff = (uint32_t)((wm * 64 + mt * 16 + a_row) * 128
                                               + (ks * 16 + a_kofs) * 2);
                    ldsm4(af[pl][mt][0], af[pl][mt][1], af[pl][mt][2], af[pl][mt][3],
                          bb + pl * 16384 + SMEM_SWIZZLE_128B(boff));
                }
            // B fragments: [plane][ng][4] ; ng covers 16 n = 2 n-tiles
            uint32_t bf_[2][2][4];
#pragma unroll
            for (int pl = 0; pl < 2; pl++)
#pragma unroll
                for (int ng = 0; ng < 2; ng++) {
                    uint32_t boff = (uint32_t)((wn * 32 + ng * 16 + b_n) * 128
                                               + (ks * 16 + b_kofs) * 2);
                    ldsm4(bf_[pl][ng][0], bf_[pl][ng][1], bf_[pl][ng][2], bf_[pl][ng][3],
                          bb + 32768 + pl * 16384 + SMEM_SWIZZLE_128B(boff));
                }
#pragma unroll
            for (int mt = 0; mt < 4; mt++)
#pragma unroll
                for (int ng = 0; ng < 2; ng++)
#pragma unroll
                    for (int hf = 0; hf < 2; hf++) {
                        float* d = acc[mt][ng * 2 + hf];
                        mma16816(d, af[0][mt], &bf_[0][ng][hf * 2]);  // a0*b0
                        mma16816(d, af[0][mt], &bf_[1][ng][hf * 2]);  // a0*b1
                        mma16816(d, af[1][mt], &bf_[0][ng][hf * 2]);  // a1*b0
                    }
        }
        __syncthreads();
    }

    // epilogue: add bias, fp32 stores (float2 per frag half)
#pragma unroll
    for (int mt = 0; mt < 4; mt++) {
        int gr = bm * 128 + wm * 64 + mt * 16 + (lane >> 2);
#pragma unroll
        for (int nt = 0; nt < 4; nt++) {
            int gc = bn * 128 + wn * 32 + nt * 8 + (lane & 3) * 2;
            float b0 = bias[gc], b1 = bias[gc + 1];
            float2 r0 = make_float2(acc[mt][nt][0] + b0, acc[mt][nt][1] + b1);
            float2 r1 = make_float2(acc[mt][nt][2] + b0, acc[mt][nt][3] + b1);
            *(float2*)(C + (size_t)gr * N + gc)       = r0;
            *(float2*)(C + (size_t)(gr + 8) * N + gc) = r1;
        }
    }
}

// ---------------- fused window attention (flash-style, online softmax) ------
#define ATTN_SMEM_FLOATS (64*68 + 64*64 + 64*68 + 64*68 + 64)
#define ATTN_SMEM_BYTES  (ATTN_SMEM_FLOATS * 4)

__global__ __launch_bounds__(256) void attn_kernel(
    const float* __restrict__ qkv, const float* __restrict__ bias_table,
    float* __restrict__ ctx)
{
    extern __shared__ float sm[];
    float* q_s   = sm;
    float* k_s   = q_s + 64 * 68;
    float* v_s   = k_s + 64 * 64;
    float* p_s   = v_s + 64 * 68;
    int*  msum_s = (int*)(p_s + 64 * 68);

    const int tid = threadIdx.x;
    const int tx  = tid & 15;
    const int ty  = tid >> 4;
    const int h   = blockIdx.y;
    const int qb  = blockIdx.x;
    const int n0  = qb * 64;
    const int qoff = h * 64;
    const int koff = 1024 + h * 64;
    const int voff = 2048 + h * 64;

    for (int idx = tid; idx < 1024; idx += 256) {
        int row = idx >> 4;
        int c4  = (idx & 15) * 4;
        float4 v = *(const float4*)(qkv + (size_t)(n0 + row) * 3072 + qoff + c4);
        v.x *= 0.125f; v.y *= 0.125f; v.z *= 0.125f; v.w *= 0.125f;
        *(float4*)&q_s[row * 68 + c4] = v;
    }

    int qsum[4];
#pragma unroll
    for (int qi = 0; qi < 4; qi++) {
        int n = n0 + ty * 4 + qi;
        qsum[qi] = (n >> 5) + (n & 31);
    }

    float mrow[4], lrow[4], o[4][4];
#pragma unroll
    for (int qi = 0; qi < 4; qi++) {
        mrow[qi] = -1e30f; lrow[qi] = 0.0f;
#pragma unroll
        for (int j = 0; j < 4; j++) o[qi][j] = 0.0f;
    }

    for (int kv = 0; kv < 16; kv++) {
        __syncthreads();
        const int m0 = kv * 64;
        for (int idx = tid; idx < 1024; idx += 256) {
            int row = idx >> 4;
            int d4  = idx & 15;
            float4 kvv = *(const float4*)(qkv + (size_t)(m0 + row) * 3072 + koff + d4 * 4);
            int dsw = d4 ^ ((row >> 2) & 7);
            *(float4*)&k_s[row * 64 + dsw * 4] = kvv;
            float4 vv = *(const float4*)(qkv + (size_t)(m0 + row) * 3072 + voff + d4 * 4);
            *(float4*)&v_s[row * 68 + d4 * 4] = vv;
        }
        if (tid < 64) {
            int m = m0 + tid;
            msum_s[tid] = (m >> 5) + (m & 31);
        }
        __syncthreads();

        float s[4][4];
#pragma unroll
        for (int qi = 0; qi < 4; qi++)
#pragma unroll
            for (int ci = 0; ci < 4; ci++) s[qi][ci] = 0.0f;

#pragma unroll
        for (int d4 = 0; d4 < 16; d4++) {
            float4 q4[4];
#pragma unroll
            for (int qi = 0; qi < 4; qi++)
                q4[qi] = *(const float4*)&q_s[(ty * 4 + qi) * 68 + d4 * 4];
#pragma unroll
            for (int ci = 0; ci < 4; ci++) {
                int c = tx * 4 + ci;
                float4 k4 = *(const float4*)&k_s[c * 64 + (d4 ^ ((c >> 2) & 7)) * 4];
#pragma unroll
                for (int qi = 0; qi < 4; qi++) {
                    s[qi][ci] += q4[qi].x * k4.x;
                    s[qi][ci] += q4[qi].y * k4.y;
                    s[qi][ci] += q4[qi].z * k4.z;
                    s[qi][ci] += q4[qi].w * k4.w;
                }
            }
        }

#pragma unroll
        for (int qi = 0; qi < 4; qi++) {
            float mx = -1e30f;
#pragma unroll
            for (int ci = 0; ci < 4; ci++) {
                int c = tx * 4 + ci;
                int bidx = 63 * (qsum[qi] - msum_s[c] + 62);
                bidx = min(bidx, 3968);
                s[qi][ci] += __ldg(&bias_table[bidx * 16 + h]);
                mx = fmaxf(mx, s[qi][ci]);
            }
            mx = fmaxf(mx, __shfl_xor_sync(0xffffffffu, mx, 1));
            mx = fmaxf(mx, __shfl_xor_sync(0xffffffffu, mx, 2));
            mx = fmaxf(mx, __shfl_xor_sync(0xffffffffu, mx, 4));
            mx = fmaxf(mx, __shfl_xor_sync(0xffffffffu, mx, 8));
            float newm = fmaxf(mrow[qi], mx);
            float corr = __expf(mrow[qi] - newm);
            float p0 = __expf(s[qi][0] - newm);
            float p1 = __expf(s[qi][1] - newm);
            float p2 = __expf(s[qi][2] - newm);
            float p3 = __expf(s[qi][3] - newm);
            float ps = p0 + p1 + p2 + p3;
            ps += __shfl_xor_sync(0xffffffffu, ps, 1);
            ps += __shfl_xor_sync(0xffffffffu, ps, 2);
            ps += __shfl_xor_sync(0xffffffffu, ps, 4);
            ps += __shfl_xor_sync(0xffffffffu, ps, 8);
            lrow[qi] = lrow[qi] * corr + ps;
            mrow[qi] = newm;
#pragma unroll
            for (int j = 0; j < 4; j++) o[qi][j] *= corr;
            *(float4*)&p_s[(ty * 4 + qi) * 68 + tx * 4] = make_float4(p0, p1, p2, p3);
        }
        __syncthreads();

#pragma unroll
        for (int c4 = 0; c4 < 16; c4++) {
            float p4[4][4];
#pragma unroll
            for (int qi = 0; qi < 4; qi++)
                *(float4*)p4[qi] = *(const float4*)&p_s[(ty * 4 + qi) * 68 + c4 * 4];
#pragma unroll
            for (int cc = 0; cc < 4; cc++) {
                float4 v4 = *(const float4*)&v_s[(c4 * 4 + cc) * 68 + tx * 4];
#pragma unroll
                for (int qi = 0; qi < 4; qi++) {
                    float pv = p4[qi][cc];
                    o[qi][0] += pv * v4.x;
                    o[qi][1] += pv * v4.y;
                    o[qi][2] += pv * v4.z;
                    o[qi][3] += pv * v4.w;
                }
            }
        }
    }

#pragma unroll
    for (int qi = 0; qi < 4; qi++) {
        float inv = 1.0f / lrow[qi];
        float4 r = make_float4(o[qi][0] * inv, o[qi][1] * inv,
                               o[qi][2] * inv, o[qi][3] * inv);
        *(float4*)(ctx + (size_t)(n0 + ty * 4 + qi) * 1024 + h * 64 + tx * 4) = r;
    }
}

// ---------------- launch -----------------------------------------------------
extern "C" void kernel_launch(void* const* d_in, const int* in_sizes, int n_in,
                              void* d_out, int out_size)
{
    const float* x          = (const float*)d_in[0];   // [1024,1024]
    const float* w_qkv      = (const float*)d_in[1];   // [3072,1024]
    const float* b_qkv      = (const float*)d_in[2];   // [3072]
    const float* w_proj     = (const float*)d_in[3];   // [1024,1024]
    const float* b_proj     = (const float*)d_in[4];   // [1024]
    const float* bias_table = (const float*)d_in[5];   // [3969,16]
    float* out = (float*)d_out;                        // [1024,1024]
    (void)in_sizes; (void)n_in; (void)out_size;

    cudaFuncSetAttribute(attn_kernel, cudaFuncAttributeMaxDynamicSharedMemorySize, ATTN_SMEM_BYTES);
    cudaFuncSetAttribute(mma_gemm, cudaFuncAttributeMaxDynamicSharedMemorySize, GEMM_SMEM_BYTES);

    float *qkv, *ctx;
    __nv_bfloat16 *x0, *x1, *wq0, *wq1, *wp0, *wp1, *c0, *c1;
    cudaGetSymbolAddress((void**)&qkv, g_qkv);
    cudaGetSymbolAddress((void**)&ctx, g_ctx);
    cudaGetSymbolAddress((void**)&x0, g_x0);     cudaGetSymbolAddress((void**)&x1, g_x1);
    cudaGetSymbolAddress((void**)&wq0, g_wqkv0); cudaGetSymbolAddress((void**)&wq1, g_wqkv1);
    cudaGetSymbolAddress((void**)&wp0, g_wp0);   cudaGetSymbolAddress((void**)&wp1, g_wp1);
    cudaGetSymbolAddress((void**)&c0, g_c0);     cudaGetSymbolAddress((void**)&c1, g_c1);

    // split fp32 -> bf16 hi/lo planes
    split_kernel<<<1024, 256>>>(x, x0, x1, 1024 * 1024);
    split_kernel<<<3072, 256>>>(w_qkv, wq0, wq1, 3072 * 1024);
    split_kernel<<<1024, 256>>>(w_proj, wp0, wp1, 1024 * 1024);

    // 1) QKV projection on tensor cores: [1024,3072] = x @ w_qkv^T + b_qkv
    mma_gemm<<<dim3(24, 8), 256, GEMM_SMEM_BYTES>>>(x0, x1, wq0, wq1, b_qkv, qkv, 3072, 1024);

    // 2) fused window attention with relative-position bias
    attn_kernel<<<dim3(16, 16), 256, ATTN_SMEM_BYTES>>>(qkv, bias_table, ctx);

    // 3) output projection on tensor cores
    split_kernel<<<1024, 256>>>(ctx, c0, c1, 1024 * 1024);
    mma_gemm<<<dim3(8, 8), 256, GEMM_SMEM_BYTES>>>(c0, c1, wp0, wp1, b_proj, out, 1024, 1024);
}

// round 6
// speedup vs baseline: 3.1778x; 1.6702x over previous
#include <cuda_runtime.h>
#include <cuda_bf16.h>
#include <cstdint>

// ---------------- scratch (device globals; no allocations allowed) ----------
__device__ __nv_bfloat16 g_qkv0[1024 * 3072], g_qkv1[1024 * 3072]; // qkv planes
__device__ __nv_bfloat16 g_x0[1024 * 1024],    g_x1[1024 * 1024];
__device__ __nv_bfloat16 g_wqkv0[3072 * 1024], g_wqkv1[3072 * 1024];
__device__ __nv_bfloat16 g_wp0[1024 * 1024],   g_wp1[1024 * 1024];
__device__ __nv_bfloat16 g_c0[1024 * 1024],    g_c1[1024 * 1024];  // ctx planes

// ---------------- helpers ----------------------------------------------------
__device__ __forceinline__ uint32_t smem_u32(const void* p) {
    uint32_t a;
    asm("{ .reg .u64 t; cvta.to.shared.u64 t, %1; cvt.u32.u64 %0, t; }" : "=r"(a) : "l"(p));
    return a;
}
#define SMEM_SWIZZLE_128B(b) ((b) ^ (((b) >> 3) & 0x70))

__device__ __forceinline__ void cp_async16(uint32_t dst, const void* src) {
    asm volatile("cp.async.cg.shared.global [%0], [%1], 16;" :: "r"(dst), "l"(src) : "memory");
}
__device__ __forceinline__ void ldsm4(uint32_t& r0, uint32_t& r1, uint32_t& r2,
                                      uint32_t& r3, uint32_t addr) {
    asm volatile("ldmatrix.sync.aligned.m8n8.x4.shared.b16 {%0,%1,%2,%3}, [%4];"
                 : "=r"(r0), "=r"(r1), "=r"(r2), "=r"(r3) : "r"(addr));
}
__device__ __forceinline__ void ldsm4t(uint32_t& r0, uint32_t& r1, uint32_t& r2,
                                       uint32_t& r3, uint32_t addr) {
    asm volatile("ldmatrix.sync.aligned.m8n8.x4.trans.shared.b16 {%0,%1,%2,%3}, [%4];"
                 : "=r"(r0), "=r"(r1), "=r"(r2), "=r"(r3) : "r"(addr));
}
__device__ __forceinline__ void mma16816(float* d, const uint32_t* a, const uint32_t* b) {
    asm volatile(
        "mma.sync.aligned.m16n8k16.row.col.f32.bf16.bf16.f32 "
        "{%0,%1,%2,%3}, {%4,%5,%6,%7}, {%8,%9}, {%0,%1,%2,%3};"
        : "+f"(d[0]), "+f"(d[1]), "+f"(d[2]), "+f"(d[3])
        : "r"(a[0]), "r"(a[1]), "r"(a[2]), "r"(a[3]), "r"(b[0]), "r"(b[1]));
}
// split a,b (fp32) into bf16 hi/lo packed pairs; a -> low half (even index)
__device__ __forceinline__ void split_pack(float a, float b, uint32_t& hi, uint32_t& lo) {
    __nv_bfloat162 h, l;
    h.x = __float2bfloat16_rn(a);
    h.y = __float2bfloat16_rn(b);
    l.x = __float2bfloat16_rn(a - __bfloat162float(h.x));
    l.y = __float2bfloat16_rn(b - __bfloat162float(h.y));
    hi = *(uint32_t*)&h;
    lo = *(uint32_t*)&l;
}

// ---------------- split fp32 -> (bf16 hi, bf16 lo) ---------------------------
__global__ __launch_bounds__(256) void split_kernel(
    const float* __restrict__ src, __nv_bfloat16* __restrict__ p0,
    __nv_bfloat16* __restrict__ p1, int n)
{
    int i = (blockIdx.x * 256 + threadIdx.x) * 4;
    if (i >= n) return;
    float4 v = *(const float4*)(src + i);
    float vv[4] = {v.x, v.y, v.z, v.w};
    __nv_bfloat16 h0[4], h1[4];
#pragma unroll
    for (int j = 0; j < 4; j++) {
        h0[j] = __float2bfloat16_rn(vv[j]);
        h1[j] = __float2bfloat16_rn(vv[j] - __bfloat162float(h0[j]));
    }
    *(uint2*)(p0 + i) = *(const uint2*)h0;
    *(uint2*)(p1 + i) = *(const uint2*)h1;
}

// ---------------- mma.sync GEMM: C = A@B^T + bias, bf16 split-2 -------------
// Output: fp32 C (if C != nullptr) or bf16 hi/lo planes P0/P1.
#define GEMM_SMEM_BYTES (2 * 4 * 16384)

__global__ __launch_bounds__(256, 1) void mma_gemm(
    const __nv_bfloat16* __restrict__ A0, const __nv_bfloat16* __restrict__ A1,
    const __nv_bfloat16* __restrict__ B0, const __nv_bfloat16* __restrict__ B1,
    const float* __restrict__ bias, float* __restrict__ C,
    __nv_bfloat16* __restrict__ P0, __nv_bfloat16* __restrict__ P1, int N, int K)
{
    extern __shared__ char smem[];
    const uint32_t sb = smem_u32(smem);
    const int tid  = threadIdx.x;
    const int lane = tid & 31;
    const int wid  = tid >> 5;
    const int wm   = wid >> 2;
    const int wn   = wid & 3;
    const int bm = blockIdx.y, bn = blockIdx.x;

    const __nv_bfloat16* planes[4];
    planes[0] = A0 + (size_t)bm * 128 * K;
    planes[1] = A1 + (size_t)bm * 128 * K;
    planes[2] = B0 + (size_t)bn * 128 * K;
    planes[3] = B1 + (size_t)bn * 128 * K;

    float acc[4][4][4];
#pragma unroll
    for (int i = 0; i < 4; i++)
#pragma unroll
        for (int j = 0; j < 4; j++)
#pragma unroll
            for (int q = 0; q < 4; q++) acc[i][j][q] = 0.0f;

    const int NCHUNK = K / 64;
    const int a_row  = lane & 15;
    const int a_kofs = (lane >> 4) * 8;
    const int b_n    = ((lane >> 4) << 3) + (lane & 7);
    const int b_kofs = lane & 8;

    auto load_chunk = [&](int c) {
        const uint32_t bb = sb + (uint32_t)(c & 1) * 65536;
        const int k0 = c * 64;
#pragma unroll
        for (int i = 0; i < 16; i++) {
            int idx  = i * 256 + tid;
            int tile = idx >> 10;
            int w    = idx & 1023;
            int row  = w >> 3;
            int j    = w & 7;
            uint32_t boff = (uint32_t)(row * 128 + j * 16);
            cp_async16(bb + tile * 16384 + SMEM_SWIZZLE_128B(boff),
                       planes[tile] + (size_t)row * K + k0 + j * 8);
        }
        asm volatile("cp.async.commit_group;" ::: "memory");
    };

    load_chunk(0);

    for (int c = 0; c < NCHUNK; c++) {
        if (c + 1 < NCHUNK) {
            load_chunk(c + 1);
            asm volatile("cp.async.wait_group 1;" ::: "memory");
        } else {
            asm volatile("cp.async.wait_group 0;" ::: "memory");
        }
        __syncthreads();

        const uint32_t bb = sb + (uint32_t)(c & 1) * 65536;
#pragma unroll
        for (int ks = 0; ks < 4; ks++) {
            uint32_t af[2][4][4];
#pragma unroll
            for (int pl = 0; pl < 2; pl++)
#pragma unroll
                for (int mt = 0; mt < 4; mt++) {
                    uint32_t boff = (uint32_t)((wm * 64 + mt * 16 + a_row) * 128
                                               + (ks * 16 + a_kofs) * 2);
                    ldsm4(af[pl][mt][0], af[pl][mt][1], af[pl][mt][2], af[pl][mt][3],
                          bb + pl * 16384 + SMEM_SWIZZLE_128B(boff));
                }
            uint32_t bf_[2][2][4];
#pragma unroll
            for (int pl = 0; pl < 2; pl++)
#pragma unroll
                for (int ng = 0; ng < 2; ng++) {
                    uint32_t boff = (uint32_t)((wn * 32 + ng * 16 + b_n) * 128
                                               + (ks * 16 + b_kofs) * 2);
                    ldsm4(bf_[pl][ng][0], bf_[pl][ng][1], bf_[pl][ng][2], bf_[pl][ng][3],
                          bb + 32768 + pl * 16384 + SMEM_SWIZZLE_128B(boff));
                }
#pragma unroll
            for (int mt = 0; mt < 4; mt++)
#pragma unroll
                for (int ng = 0; ng < 2; ng++)
#pragma unroll
                    for (int hf = 0; hf < 2; hf++) {
                        float* d = acc[mt][ng * 2 + hf];
                        mma16816(d, af[0][mt], &bf_[0][ng][hf * 2]);
                        mma16816(d, af[0][mt], &bf_[1][ng][hf * 2]);
                        mma16816(d, af[1][mt], &bf_[0][ng][hf * 2]);
                    }
        }
        __syncthreads();
    }

#pragma unroll
    for (int mt = 0; mt < 4; mt++) {
        int gr = bm * 128 + wm * 64 + mt * 16 + (lane >> 2);
#pragma unroll
        for (int nt = 0; nt < 4; nt++) {
            int gc = bn * 128 + wn * 32 + nt * 8 + (lane & 3) * 2;
            float b0 = bias[gc], b1 = bias[gc + 1];
            float v0 = acc[mt][nt][0] + b0, v1 = acc[mt][nt][1] + b1;
            float v2 = acc[mt][nt][2] + b0, v3 = acc[mt][nt][3] + b1;
            if (C) {
                *(float2*)(C + (size_t)gr * N + gc)       = make_float2(v0, v1);
                *(float2*)(C + (size_t)(gr + 8) * N + gc) = make_float2(v2, v3);
            } else {
                uint32_t hi, lo;
                split_pack(v0, v1, hi, lo);
                *(uint32_t*)(P0 + (size_t)gr * N + gc) = hi;
                *(uint32_t*)(P1 + (size_t)gr * N + gc) = lo;
                split_pack(v2, v3, hi, lo);
                *(uint32_t*)(P0 + (size_t)(gr + 8) * N + gc) = hi;
                *(uint32_t*)(P1 + (size_t)(gr + 8) * N + gc) = lo;
            }
        }
    }
}

// ---------------- tensor-core flash attention (split-2 bf16) -----------------
// Grid (8 q-blocks of 128 rows, 16 heads), 256 threads = 8 warps.
// Warp w owns q-rows [qb*128 + w*16, +16). Per 64-kv chunk: S-mma (3 passes),
// online softmax on fragments, P repack (C->A identity), PV-mma with ldsm.trans.
// smem: Q planes 2x16KB | KV double buffer 2 x (k0,k1,v0,v1 @ 8KB) | 125-fl LUT
#define ATTN_SMEM_BYTES (32768 + 65536 + 512)

__global__ __launch_bounds__(256, 1) void attn_mma(
    const __nv_bfloat16* __restrict__ qkv0, const __nv_bfloat16* __restrict__ qkv1,
    const float* __restrict__ bias_table,
    __nv_bfloat16* __restrict__ c0, __nv_bfloat16* __restrict__ c1)
{
    extern __shared__ char smem[];
    const uint32_t sb = smem_u32(smem);
    const uint32_t Q0 = sb, Q1 = sb + 16384;
    const uint32_t KV = sb + 32768;           // + (c&1)*32768 ; tiles of 8192
    float* lut = (float*)(smem + 98304);

    const int tid  = threadIdx.x;
    const int lane = tid & 31;
    const int warp = tid >> 5;
    const int h    = blockIdx.y;
    const int qb   = blockIdx.x;
    const int q0r  = qb * 128;

    // per-head bias LUT over delta = qsum - msum in [-62, 62]
    if (tid < 125) {
        int idx = min(63 * tid, 3968);
        lut[tid] = bias_table[idx * 16 + h];
    }

    // ---- async load Q planes (128 rows x 64 dh) ----
#pragma unroll
    for (int i = 0; i < 8; i++) {
        int idx = i * 256 + tid;
        int pl  = idx >> 10;
        int w   = idx & 1023;
        int row = w >> 3;
        int seg = w & 7;
        const __nv_bfloat16* src = (pl ? qkv1 : qkv0)
            + (size_t)(q0r + row) * 3072 + h * 64 + seg * 8;
        cp_async16((pl ? Q1 : Q0) + SMEM_SWIZZLE_128B((uint32_t)(row * 128 + seg * 16)), src);
    }

    auto load_kv = [&](int c) {
        const uint32_t bb = KV + (uint32_t)(c & 1) * 32768;
        const int m0 = c * 64;
#pragma unroll
        for (int i = 0; i < 8; i++) {
            int idx = i * 256 + tid;
            int tile = idx >> 9;            // 0:k0 1:k1 2:v0 3:v1
            int w    = idx & 511;
            int row  = w >> 3;
            int seg  = w & 7;
            const __nv_bfloat16* base = (tile & 1) ? qkv1 : qkv0;
            int off = (tile >> 1) ? 2048 : 1024;
            cp_async16(bb + tile * 8192 + SMEM_SWIZZLE_128B((uint32_t)(row * 128 + seg * 16)),
                       base + (size_t)(m0 + row) * 3072 + off + h * 64 + seg * 8);
        }
        asm volatile("cp.async.commit_group;" ::: "memory");
    };

    load_kv(0);   // group 0 = Q + chunk0

    // ldmatrix address components
    const int a_row  = lane & 15;
    const int a_kofs = (lane >> 4) * 8;
    const int b_n    = ((lane >> 4) << 3) + (lane & 7);
    const int b_kofs = lane & 8;
    // V trans: lanes give source rows (kv), tiles (kvlo/hi x dhlo/hi)
    const int v_kv = ((lane >> 3) & 1) * 8 + (lane & 7);
    const int v_dh = (lane >> 4) * 8;

    const int r0g = q0r + warp * 16 + (lane >> 2);
    const int r1g = r0g + 8;
    const int qs0 = (r0g >> 5) + (r0g & 31);
    const int qs1 = (r1g >> 5) + (r1g & 31);

    uint32_t qa[2][4][4];     // [plane][kstep][frag]
    float oacc[8][4];
#pragma unroll
    for (int j = 0; j < 8; j++)
#pragma unroll
        for (int q = 0; q < 4; q++) oacc[j][q] = 0.0f;
    float m0r = -1e30f, m1r = -1e30f, l0 = 0.0f, l1 = 0.0f;

    for (int c = 0; c < 16; c++) {
        if (c + 1 < 16) {
            load_kv(c + 1);
            asm volatile("cp.async.wait_group 1;" ::: "memory");
        } else {
            asm volatile("cp.async.wait_group 0;" ::: "memory");
        }
        __syncthreads();

        if (c == 0) {   // Q frags resident for whole kernel
#pragma unroll
            for (int pl = 0; pl < 2; pl++)
#pragma unroll
                for (int ks = 0; ks < 4; ks++) {
                    uint32_t boff = (uint32_t)((warp * 16 + a_row) * 128
                                               + (ks * 16 + a_kofs) * 2);
                    ldsm4(qa[pl][ks][0], qa[pl][ks][1], qa[pl][ks][2], qa[pl][ks][3],
                          (pl ? Q1 : Q0) + SMEM_SWIZZLE_128B(boff));
                }
        }

        const uint32_t bb = KV + (uint32_t)(c & 1) * 32768;

        // ---- S = Q K^T (3 split passes) ----
        float s[8][4];
#pragma unroll
        for (int j = 0; j < 8; j++)
#pragma unroll
            for (int q = 0; q < 4; q++) s[j][q] = 0.0f;

#pragma unroll
        for (int ks = 0; ks < 4; ks++)
#pragma unroll
            for (int ng = 0; ng < 4; ng++) {
                uint32_t boff = SMEM_SWIZZLE_128B(
                    (uint32_t)((ng * 16 + b_n) * 128 + (ks * 16 + b_kofs) * 2));
                uint32_t kb0[4], kb1[4];
                ldsm4(kb0[0], kb0[1], kb0[2], kb0[3], bb + boff);
                ldsm4(kb1[0], kb1[1], kb1[2], kb1[3], bb + 8192 + boff);
#pragma unroll
                for (int hf = 0; hf < 2; hf++) {
                    float* d = s[ng * 2 + hf];
                    mma16816(d, qa[0][ks], &kb0[hf * 2]);
                    mma16816(d, qa[0][ks], &kb1[hf * 2]);
                    mma16816(d, qa[1][ks], &kb0[hf * 2]);
                }
            }

        // ---- scale + bias + online softmax ----
        const int mbase = c * 64;
        float mx0 = -1e30f, mx1 = -1e30f;
#pragma unroll
        for (int j = 0; j < 8; j++) {
            int mc  = mbase + 8 * j + 2 * (lane & 3);
            int ms0 = (mc >> 5) + (mc & 31);
            int ms1 = ((mc + 1) >> 5) + ((mc + 1) & 31);
            s[j][0] = s[j][0] * 0.125f + lut[qs0 - ms0 + 62];
            s[j][1] = s[j][1] * 0.125f + lut[qs0 - ms1 + 62];
            s[j][2] = s[j][2] * 0.125f + lut[qs1 - ms0 + 62];
            s[j][3] = s[j][3] * 0.125f + lut[qs1 - ms1 + 62];
            mx0 = fmaxf(mx0, fmaxf(s[j][0], s[j][1]));
            mx1 = fmaxf(mx1, fmaxf(s[j][2], s[j][3]));
        }
        mx0 = fmaxf(mx0, __shfl_xor_sync(0xffffffffu, mx0, 1));
        mx0 = fmaxf(mx0, __shfl_xor_sync(0xffffffffu, mx0, 2));
        mx1 = fmaxf(mx1, __shfl_xor_sync(0xffffffffu, mx1, 1));
        mx1 = fmaxf(mx1, __shfl_xor_sync(0xffffffffu, mx1, 2));
        float nm0 = fmaxf(m0r, mx0), nm1 = fmaxf(m1r, mx1);
        float cr0 = __expf(m0r - nm0), cr1 = __expf(m1r - nm1);
        float ps0 = 0.0f, ps1 = 0.0f;
#pragma unroll
        for (int j = 0; j < 8; j++) {
            s[j][0] = __expf(s[j][0] - nm0);
            s[j][1] = __expf(s[j][1] - nm0);
            s[j][2] = __expf(s[j][2] - nm1);
            s[j][3] = __expf(s[j][3] - nm1);
            ps0 += s[j][0] + s[j][1];
            ps1 += s[j][2] + s[j][3];
        }
        ps0 += __shfl_xor_sync(0xffffffffu, ps0, 1);
        ps0 += __shfl_xor_sync(0xffffffffu, ps0, 2);
        ps1 += __shfl_xor_sync(0xffffffffu, ps1, 1);
        ps1 += __shfl_xor_sync(0xffffffffu, ps1, 2);
        l0 = l0 * cr0 + ps0;
        l1 = l1 * cr1 + ps1;
        m0r = nm0; m1r = nm1;
#pragma unroll
        for (int j = 0; j < 8; j++) {
            oacc[j][0] *= cr0; oacc[j][1] *= cr0;
            oacc[j][2] *= cr1; oacc[j][3] *= cr1;
        }

        // ---- repack P into A-frags (split-2) ----
        uint32_t p0a[4][4], p1a[4][4];
#pragma unroll
        for (int ks = 0; ks < 4; ks++) {
            int j0 = 2 * ks, j1 = 2 * ks + 1;
            split_pack(s[j0][0], s[j0][1], p0a[ks][0], p1a[ks][0]);
            split_pack(s[j0][2], s[j0][3], p0a[ks][1], p1a[ks][1]);
            split_pack(s[j1][0], s[j1][1], p0a[ks][2], p1a[ks][2]);
            split_pack(s[j1][2], s[j1][3], p0a[ks][3], p1a[ks][3]);
        }

        // ---- O += P V (3 split passes), V via ldmatrix.trans ----
#pragma unroll
        for (int ks = 0; ks < 4; ks++)
#pragma unroll
            for (int dg = 0; dg < 4; dg++) {
                uint32_t boff = SMEM_SWIZZLE_128B(
                    (uint32_t)((ks * 16 + v_kv) * 128 + (dg * 16 + v_dh) * 2));
                uint32_t vb0[4], vb1[4];
                ldsm4t(vb0[0], vb0[1], vb0[2], vb0[3], bb + 16384 + boff);
                ldsm4t(vb1[0], vb1[1], vb1[2], vb1[3], bb + 24576 + boff);
#pragma unroll
                for (int hf = 0; hf < 2; hf++) {
                    float* d = oacc[dg * 2 + hf];
                    mma16816(d, p0a[ks], &vb0[hf * 2]);
                    mma16816(d, p0a[ks], &vb1[hf * 2]);
                    mma16816(d, p1a[ks], &vb0[hf * 2]);
                }
            }
        __syncthreads();
    }

    // ---- normalize, split, write ctx planes ----
    float inv0 = 1.0f / l0, inv1 = 1.0f / l1;
#pragma unroll
    for (int j = 0; j < 8; j++) {
        int col = h * 64 + 8 * j + 2 * (lane & 3);
        uint32_t hi, lo;
        split_pack(oacc[j][0] * inv0, oacc[j][1] * inv0, hi, lo);
        *(uint32_t*)(c0 + (size_t)r0g * 1024 + col) = hi;
        *(uint32_t*)(c1 + (size_t)r0g * 1024 + col) = lo;
        split_pack(oacc[j][2] * inv1, oacc[j][3] * inv1, hi, lo);
        *(uint32_t*)(c0 + (size_t)r1g * 1024 + col) = hi;
        *(uint32_t*)(c1 + (size_t)r1g * 1024 + col) = lo;
    }
}

// ---------------- launch -----------------------------------------------------
extern "C" void kernel_launch(void* const* d_in, const int* in_sizes, int n_in,
                              void* d_out, int out_size)
{
    const float* x          = (const float*)d_in[0];
    const float* w_qkv      = (const float*)d_in[1];
    const float* b_qkv      = (const float*)d_in[2];
    const float* w_proj     = (const float*)d_in[3];
    const float* b_proj     = (const float*)d_in[4];
    const float* bias_table = (const float*)d_in[5];
    float* out = (float*)d_out;
    (void)in_sizes; (void)n_in; (void)out_size;

    cudaFuncSetAttribute(mma_gemm, cudaFuncAttributeMaxDynamicSharedMemorySize, GEMM_SMEM_BYTES);
    cudaFuncSetAttribute(attn_mma, cudaFuncAttributeMaxDynamicSharedMemorySize, ATTN_SMEM_BYTES);

    __nv_bfloat16 *qkv0, *qkv1, *x0, *x1, *wq0, *wq1, *wp0, *wp1, *c0, *c1;
    cudaGetSymbolAddress((void**)&qkv0, g_qkv0);  cudaGetSymbolAddress((void**)&qkv1, g_qkv1);
    cudaGetSymbolAddress((void**)&x0, g_x0);      cudaGetSymbolAddress((void**)&x1, g_x1);
    cudaGetSymbolAddress((void**)&wq0, g_wqkv0);  cudaGetSymbolAddress((void**)&wq1, g_wqkv1);
    cudaGetSymbolAddress((void**)&wp0, g_wp0);    cudaGetSymbolAddress((void**)&wp1, g_wp1);
    cudaGetSymbolAddress((void**)&c0, g_c0);      cudaGetSymbolAddress((void**)&c1, g_c1);

    // split inputs/weights into bf16 hi/lo planes
    split_kernel<<<1024, 256>>>(x, x0, x1, 1024 * 1024);
    split_kernel<<<3072, 256>>>(w_qkv, wq0, wq1, 3072 * 1024);
    split_kernel<<<1024, 256>>>(w_proj, wp0, wp1, 1024 * 1024);

    // 1) QKV projection -> bf16 planes directly (no fp32 intermediate)
    mma_gemm<<<dim3(24, 8), 256, GEMM_SMEM_BYTES>>>(
        x0, x1, wq0, wq1, b_qkv, nullptr, qkv0, qkv1, 3072, 1024);

    // 2) tensor-core flash attention -> ctx bf16 planes
    attn_mma<<<dim3(8, 16), 256, ATTN_SMEM_BYTES>>>(qkv0, qkv1, bias_table, c0, c1);

    // 3) output projection -> fp32 out
    mma_gemm<<<dim3(8, 8), 256, GEMM_SMEM_BYTES>>>(
        c0, c1, wp0, wp1, b_proj, out, nullptr, nullptr, 1024, 1024);
}

// round 8
// speedup vs baseline: 3.5701x; 1.1234x over previous
#include <cuda_runtime.h>
#include <cuda_bf16.h>
#include <cstdint>

// ---------------- scratch (device globals; no allocations allowed) ----------
__device__ __nv_bfloat16 g_qkv0[1024 * 3072], g_qkv1[1024 * 3072]; // qkv planes
__device__ __nv_bfloat16 g_x0[1024 * 1024],    g_x1[1024 * 1024];
__device__ __nv_bfloat16 g_wqkv0[3072 * 1024], g_wqkv1[3072 * 1024];
__device__ __nv_bfloat16 g_wp0[1024 * 1024],   g_wp1[1024 * 1024];
__device__ __nv_bfloat16 g_c0[1024 * 1024],    g_c1[1024 * 1024];  // ctx planes

// ---------------- helpers ----------------------------------------------------
__device__ __forceinline__ uint32_t smem_u32(const void* p) {
    uint32_t a;
    asm("{ .reg .u64 t; cvta.to.shared.u64 t, %1; cvt.u32.u64 %0, t; }" : "=r"(a) : "l"(p));
    return a;
}
#define SMEM_SWIZZLE_128B(b) ((b) ^ (((b) >> 3) & 0x70))
// 64-byte-row tile swizzle: row r, 16B chunk j (0..3) -> conflict-free ldmatrix
#define GSWZ(r, j) ((uint32_t)((r) * 64 + ((((j) ^ (((r) >> 1) & 3))) << 4)))

__device__ __forceinline__ void cp_async16(uint32_t dst, const void* src) {
    asm volatile("cp.async.cg.shared.global [%0], [%1], 16;" :: "r"(dst), "l"(src) : "memory");
}
__device__ __forceinline__ void ldsm4(uint32_t& r0, uint32_t& r1, uint32_t& r2,
                                      uint32_t& r3, uint32_t addr) {
    asm volatile("ldmatrix.sync.aligned.m8n8.x4.shared.b16 {%0,%1,%2,%3}, [%4];"
                 : "=r"(r0), "=r"(r1), "=r"(r2), "=r"(r3) : "r"(addr));
}
__device__ __forceinline__ void ldsm4t(uint32_t& r0, uint32_t& r1, uint32_t& r2,
                                       uint32_t& r3, uint32_t addr) {
    asm volatile("ldmatrix.sync.aligned.m8n8.x4.trans.shared.b16 {%0,%1,%2,%3}, [%4];"
                 : "=r"(r0), "=r"(r1), "=r"(r2), "=r"(r3) : "r"(addr));
}
__device__ __forceinline__ void mma16816(float* d, const uint32_t* a, const uint32_t* b) {
    asm volatile(
        "mma.sync.aligned.m16n8k16.row.col.f32.bf16.bf16.f32 "
        "{%0,%1,%2,%3}, {%4,%5,%6,%7}, {%8,%9}, {%0,%1,%2,%3};"
        : "+f"(d[0]), "+f"(d[1]), "+f"(d[2]), "+f"(d[3])
        : "r"(a[0]), "r"(a[1]), "r"(a[2]), "r"(a[3]), "r"(b[0]), "r"(b[1]));
}
__device__ __forceinline__ void split_pack(float a, float b, uint32_t& hi, uint32_t& lo) {
    __nv_bfloat162 h, l;
    h.x = __float2bfloat16_rn(a);
    h.y = __float2bfloat16_rn(b);
    l.x = __float2bfloat16_rn(a - __bfloat162float(h.x));
    l.y = __float2bfloat16_rn(b - __bfloat162float(h.y));
    hi = *(uint32_t*)&h;
    lo = *(uint32_t*)&l;
}

// ---------------- merged split fp32 -> (bf16 hi, bf16 lo) --------------------
// blocks [0,1024): x ; [1024,4096): w_qkv ; [4096,5120): w_proj
__global__ __launch_bounds__(256) void split_all(
    const float* __restrict__ x, const float* __restrict__ wq,
    const float* __restrict__ wp,
    __nv_bfloat16* __restrict__ x0, __nv_bfloat16* __restrict__ x1,
    __nv_bfloat16* __restrict__ q0, __nv_bfloat16* __restrict__ q1,
    __nv_bfloat16* __restrict__ p0, __nv_bfloat16* __restrict__ p1)
{
    int b = blockIdx.x;
    const float* src;
    __nv_bfloat16 *d0, *d1;
    int base;
    if (b < 1024)      { src = x;  d0 = x0; d1 = x1; base = b; }
    else if (b < 4096) { src = wq; d0 = q0; d1 = q1; base = b - 1024; }
    else               { src = wp; d0 = p0; d1 = p1; base = b - 4096; }
    int i = base * 1024 + threadIdx.x * 4;
    float4 v = *(const float4*)(src + i);
    float vv[4] = {v.x, v.y, v.z, v.w};
    __nv_bfloat16 h0[4], h1[4];
#pragma unroll
    for (int j = 0; j < 4; j++) {
        h0[j] = __float2bfloat16_rn(vv[j]);
        h1[j] = __float2bfloat16_rn(vv[j] - __bfloat162float(h0[j]));
    }
    *(uint2*)(d0 + i) = *(const uint2*)h0;
    *(uint2*)(d1 + i) = *(const uint2*)h1;
}

// ---------------- mma.sync GEMM: C = A@B^T + bias, bf16 split-2 -------------
// BM=64, BN=128, K-chunk 32, triple-buffered smem (3 x 24KB), 2 CTAs/SM.
// 8 warps: warp (wm 0..3, wn 0..1) owns 16 rows x 64 cols = 8 m16n8 frags.
// Buffer layout: [A0 4KB][A1 4KB][B0 8KB][B1 8KB], 64B rows, GSWZ swizzle.
#define GEMM_SMEM_BYTES (3 * 24576)

__global__ __launch_bounds__(256, 2) void mma_gemm(
    const __nv_bfloat16* __restrict__ A0, const __nv_bfloat16* __restrict__ A1,
    const __nv_bfloat16* __restrict__ B0, const __nv_bfloat16* __restrict__ B1,
    const float* __restrict__ bias, float* __restrict__ C,
    __nv_bfloat16* __restrict__ P0, __nv_bfloat16* __restrict__ P1, int N, int K)
{
    extern __shared__ char smem[];
    const uint32_t sb = smem_u32(smem);
    const int tid  = threadIdx.x;
    const int lane = tid & 31;
    const int wid  = tid >> 5;
    const int wm   = wid & 3;           // 16-row group
    const int wn   = wid >> 2;          // 64-col group
    const int bm = blockIdx.y, bn = blockIdx.x;

    const __nv_bfloat16* pa0 = A0 + (size_t)bm * 64 * K;
    const __nv_bfloat16* pa1 = A1 + (size_t)bm * 64 * K;
    const __nv_bfloat16* pb0 = B0 + (size_t)bn * 128 * K;
    const __nv_bfloat16* pb1 = B1 + (size_t)bn * 128 * K;

    float acc[8][4];
#pragma unroll
    for (int i = 0; i < 8; i++)
#pragma unroll
        for (int q = 0; q < 4; q++) acc[i][q] = 0.0f;

    const int NCH = K / 32;

    auto load_chunk = [&](int c) {
        const uint32_t bb = sb + (uint32_t)(c % 3) * 24576;
        const int k0 = c * 32;
#pragma unroll
        for (int i = 0; i < 2; i++) {           // A planes: 512 cp16
            int idx = i * 256 + tid;
            int pl = idx >> 8, w = idx & 255;
            int row = w >> 2, j = w & 3;
            cp_async16(bb + pl * 4096 + GSWZ(row, j),
                       (pl ? pa1 : pa0) + (size_t)row * K + k0 + j * 8);
        }
#pragma unroll
        for (int i = 0; i < 4; i++) {           // B planes: 1024 cp16
            int idx = i * 256 + tid;
            int pl = idx >> 9, w = idx & 511;
            int row = w >> 2, j = w & 3;
            cp_async16(bb + 8192 + pl * 8192 + GSWZ(row, j),
                       (pl ? pb1 : pb0) + (size_t)row * K + k0 + j * 8);
        }
        asm volatile("cp.async.commit_group;" ::: "memory");
    };

    load_chunk(0);
    load_chunk(1);

    // ldmatrix lane address components
    const int a_row = lane & 15;
    const int a_j   = lane >> 4;               // k half (0/1)
    const int b_row = ((lane >> 4) << 3) + (lane & 7);
    const int b_j   = (lane >> 3) & 1;

    for (int c = 0; c < NCH; c++) {
        asm volatile("cp.async.wait_group 1;" ::: "memory");
        __syncthreads();
        if (c + 2 < NCH) load_chunk(c + 2);

        const uint32_t bb = sb + (uint32_t)(c % 3) * 24576;
#pragma unroll
        for (int ks = 0; ks < 2; ks++) {
            uint32_t bf[2][4][4];
#pragma unroll
            for (int pl = 0; pl < 2; pl++)
#pragma unroll
                for (int ng = 0; ng < 4; ng++) {
                    int row = wn * 64 + ng * 16 + b_row;
                    ldsm4(bf[pl][ng][0], bf[pl][ng][1], bf[pl][ng][2], bf[pl][ng][3],
                          bb + 8192 + pl * 8192 + GSWZ(row, ks * 2 + b_j));
                }
            uint32_t af0[4], af1[4];
            {
                int row = wm * 16 + a_row;
                ldsm4(af0[0], af0[1], af0[2], af0[3], bb + GSWZ(row, ks * 2 + a_j));
                ldsm4(af1[0], af1[1], af1[2], af1[3], bb + 4096 + GSWZ(row, ks * 2 + a_j));
            }
#pragma unroll
            for (int ng = 0; ng < 4; ng++)
#pragma unroll
                for (int hf = 0; hf < 2; hf++) {
                    float* d = acc[ng * 2 + hf];
                    mma16816(d, af0, &bf[0][ng][hf * 2]);
                    mma16816(d, af0, &bf[1][ng][hf * 2]);
                    mma16816(d, af1, &bf[0][ng][hf * 2]);
                }
        }
        __syncthreads();
    }

    // epilogue
    const int gr = bm * 64 + wm * 16 + (lane >> 2);
#pragma unroll
    for (int nt = 0; nt < 8; nt++) {
        int gc = bn * 128 + wn * 64 + nt * 8 + (lane & 3) * 2;
        float b0 = bias[gc], b1 = bias[gc + 1];
        float v0 = acc[nt][0] + b0, v1 = acc[nt][1] + b1;
        float v2 = acc[nt][2] + b0, v3 = acc[nt][3] + b1;
        if (C) {
            *(float2*)(C + (size_t)gr * N + gc)       = make_float2(v0, v1);
            *(float2*)(C + (size_t)(gr + 8) * N + gc) = make_float2(v2, v3);
        } else {
            uint32_t hi, lo;
            split_pack(v0, v1, hi, lo);
            *(uint32_t*)(P0 + (size_t)gr * N + gc) = hi;
            *(uint32_t*)(P1 + (size_t)gr * N + gc) = lo;
            split_pack(v2, v3, hi, lo);
            *(uint32_t*)(P0 + (size_t)(gr + 8) * N + gc) = hi;
            *(uint32_t*)(P1 + (size_t)(gr + 8) * N + gc) = lo;
        }
    }
}

// ---------------- tensor-core flash attention (split-2 bf16) -----------------
// Grid (8 q-blocks of 128 rows, 16 heads), 256 threads = 8 warps.
#define ATTN_SMEM_BYTES (32768 + 65536 + 512)

__global__ __launch_bounds__(256, 1) void attn_mma(
    const __nv_bfloat16* __restrict__ qkv0, const __nv_bfloat16* __restrict__ qkv1,
    const float* __restrict__ bias_table,
    __nv_bfloat16* __restrict__ c0, __nv_bfloat16* __restrict__ c1)
{
    extern __shared__ char smem[];
    const uint32_t sb = smem_u32(smem);
    const uint32_t Q0 = sb, Q1 = sb + 16384;
    const uint32_t KV = sb + 32768;
    float* lut = (float*)(smem + 98304);

    const int tid  = threadIdx.x;
    const int lane = tid & 31;
    const int warp = tid >> 5;
    const int h    = blockIdx.y;
    const int qb   = blockIdx.x;
    const int q0r  = qb * 128;

    if (tid < 125) {
        int idx = min(63 * tid, 3968);
        lut[tid] = bias_table[idx * 16 + h];
    }

#pragma unroll
    for (int i = 0; i < 8; i++) {
        int idx = i * 256 + tid;
        int pl  = idx >> 10;
        int w   = idx & 1023;
        int row = w >> 3;
        int seg = w & 7;
        const __nv_bfloat16* src = (pl ? qkv1 : qkv0)
            + (size_t)(q0r + row) * 3072 + h * 64 + seg * 8;
        cp_async16((pl ? Q1 : Q0) + SMEM_SWIZZLE_128B((uint32_t)(row * 128 + seg * 16)), src);
    }

    auto load_kv = [&](int c) {
        const uint32_t bb = KV + (uint32_t)(c & 1) * 32768;
        const int m0 = c * 64;
#pragma unroll
        for (int i = 0; i < 8; i++) {
            int idx = i * 256 + tid;
            int tile = idx >> 9;
            int w    = idx & 511;
            int row  = w >> 3;
            int seg  = w & 7;
            const __nv_bfloat16* base = (tile & 1) ? qkv1 : qkv0;
            int off = (tile >> 1) ? 2048 : 1024;
            cp_async16(bb + tile * 8192 + SMEM_SWIZZLE_128B((uint32_t)(row * 128 + seg * 16)),
                       base + (size_t)(m0 + row) * 3072 + off + h * 64 + seg * 8);
        }
        asm volatile("cp.async.commit_group;" ::: "memory");
    };

    load_kv(0);

    const int a_row  = lane & 15;
    const int a_kofs = (lane >> 4) * 8;
    const int b_n    = ((lane >> 4) << 3) + (lane & 7);
    const int b_kofs = lane & 8;
    const int v_kv = ((lane >> 3) & 1) * 8 + (lane & 7);
    const int v_dh = (lane >> 4) * 8;

    const int r0g = q0r + warp * 16 + (lane >> 2);
    const int r1g = r0g + 8;
    const int qs0 = (r0g >> 5) + (r0g & 31);
    const int qs1 = (r1g >> 5) + (r1g & 31);

    uint32_t qa[2][4][4];
    float oacc[8][4];
#pragma unroll
    for (int j = 0; j < 8; j++)
#pragma unroll
        for (int q = 0; q < 4; q++) oacc[j][q] = 0.0f;
    float m0r = -1e30f, m1r = -1e30f, l0 = 0.0f, l1 = 0.0f;

    for (int c = 0; c < 16; c++) {
        if (c + 1 < 16) {
            load_kv(c + 1);
            asm volatile("cp.async.wait_group 1;" ::: "memory");
        } else {
            asm volatile("cp.async.wait_group 0;" ::: "memory");
        }
        __syncthreads();

        if (c == 0) {
#pragma unroll
            for (int pl = 0; pl < 2; pl++)
#pragma unroll
                for (int ks = 0; ks < 4; ks++) {
                    uint32_t boff = (uint32_t)((warp * 16 + a_row) * 128
                                               + (ks * 16 + a_kofs) * 2);
                    ldsm4(qa[pl][ks][0], qa[pl][ks][1], qa[pl][ks][2], qa[pl][ks][3],
                          (pl ? Q1 : Q0) + SMEM_SWIZZLE_128B(boff));
                }
        }

        const uint32_t bb = KV + (uint32_t)(c & 1) * 32768;

        float s[8][4];
#pragma unroll
        for (int j = 0; j < 8; j++)
#pragma unroll
            for (int q = 0; q < 4; q++) s[j][q] = 0.0f;

#pragma unroll
        for (int ks = 0; ks < 4; ks++)
#pragma unroll
            for (int ng = 0; ng < 4; ng++) {
                uint32_t boff = SMEM_SWIZZLE_128B(
                    (uint32_t)((ng * 16 + b_n) * 128 + (ks * 16 + b_kofs) * 2));
                uint32_t kb0[4], kb1[4];
                ldsm4(kb0[0], kb0[1], kb0[2], kb0[3], bb + boff);
                ldsm4(kb1[0], kb1[1], kb1[2], kb1[3], bb + 8192 + boff);
#pragma unroll
                for (int hf = 0; hf < 2; hf++) {
                    float* d = s[ng * 2 + hf];
                    mma16816(d, qa[0][ks], &kb0[hf * 2]);
                    mma16816(d, qa[0][ks], &kb1[hf * 2]);
                    mma16816(d, qa[1][ks], &kb0[hf * 2]);
                }
            }

        const int mbase = c * 64;
        float mx0 = -1e30f, mx1 = -1e30f;
#pragma unroll
        for (int j = 0; j < 8; j++) {
            int mc  = mbase + 8 * j + 2 * (lane & 3);
            int ms0 = (mc >> 5) + (mc & 31);
            int ms1 = ((mc + 1) >> 5) + ((mc + 1) & 31);
            s[j][0] = s[j][0] * 0.125f + lut[qs0 - ms0 + 62];
            s[j][1] = s[j][1] * 0.125f + lut[qs0 - ms1 + 62];
            s[j][2] = s[j][2] * 0.125f + lut[qs1 - ms0 + 62];
            s[j][3] = s[j][3] * 0.125f + lut[qs1 - ms1 + 62];
            mx0 = fmaxf(mx0, fmaxf(s[j][0], s[j][1]));
            mx1 = fmaxf(mx1, fmaxf(s[j][2], s[j][3]));
        }
        mx0 = fmaxf(mx0, __shfl_xor_sync(0xffffffffu, mx0, 1));
        mx0 = fmaxf(mx0, __shfl_xor_sync(0xffffffffu, mx0, 2));
        mx1 = fmaxf(mx1, __shfl_xor_sync(0xffffffffu, mx1, 1));
        mx1 = fmaxf(mx1, __shfl_xor_sync(0xffffffffu, mx1, 2));
        float nm0 = fmaxf(m0r, mx0), nm1 = fmaxf(m1r, mx1);
        float cr0 = __expf(m0r - nm0), cr1 = __expf(m1r - nm1);
        float ps0 = 0.0f, ps1 = 0.0f;
#pragma unroll
        for (int j = 0; j < 8; j++) {
            s[j][0] = __expf(s[j][0] - nm0);
            s[j][1] = __expf(s[j][1] - nm0);
            s[j][2] = __expf(s[j][2] - nm1);
            s[j][3] = __expf(s[j][3] - nm1);
            ps0 += s[j][0] + s[j][1];
            ps1 += s[j][2] + s[j][3];
        }
        ps0 += __shfl_xor_sync(0xffffffffu, ps0, 1);
        ps0 += __shfl_xor_sync(0xffffffffu, ps0, 2);
        ps1 += __shfl_xor_sync(0xffffffffu, ps1, 1);
        ps1 += __shfl_xor_sync(0xffffffffu, ps1, 2);
        l0 = l0 * cr0 + ps0;
        l1 = l1 * cr1 + ps1;
        m0r = nm0; m1r = nm1;
#pragma unroll
        for (int j = 0; j < 8; j++) {
            oacc[j][0] *= cr0; oacc[j][1] *= cr0;
            oacc[j][2] *= cr1; oacc[j][3] *= cr1;
        }

        uint32_t p0a[4][4], p1a[4][4];
#pragma unroll
        for (int ks = 0; ks < 4; ks++) {
            int j0 = 2 * ks, j1 = 2 * ks + 1;
            split_pack(s[j0][0], s[j0][1], p0a[ks][0], p1a[ks][0]);
            split_pack(s[j0][2], s[j0][3], p0a[ks][1], p1a[ks][1]);
            split_pack(s[j1][0], s[j1][1], p0a[ks][2], p1a[ks][2]);
            split_pack(s[j1][2], s[j1][3], p0a[ks][3], p1a[ks][3]);
        }

#pragma unroll
        for (int ks = 0; ks < 4; ks++)
#pragma unroll
            for (int dg = 0; dg < 4; dg++) {
                uint32_t boff = SMEM_SWIZZLE_128B(
                    (uint32_t)((ks * 16 + v_kv) * 128 + (dg * 16 + v_dh) * 2));
                uint32_t vb0[4], vb1[4];
                ldsm4t(vb0[0], vb0[1], vb0[2], vb0[3], bb + 16384 + boff);
                ldsm4t(vb1[0], vb1[1], vb1[2], vb1[3], bb + 24576 + boff);
#pragma unroll
                for (int hf = 0; hf < 2; hf++) {
                    float* d = oacc[dg * 2 + hf];
                    mma16816(d, p0a[ks], &vb0[hf * 2]);
                    mma16816(d, p0a[ks], &vb1[hf * 2]);
                    mma16816(d, p1a[ks], &vb0[hf * 2]);
                }
            }
        __syncthreads();
    }

    float inv0 = 1.0f / l0, inv1 = 1.0f / l1;
#pragma unroll
    for (int j = 0; j < 8; j++) {
        int col = h * 64 + 8 * j + 2 * (lane & 3);
        uint32_t hi, lo;
        split_pack(oacc[j][0] * inv0, oacc[j][1] * inv0, hi, lo);
        *(uint32_t*)(c0 + (size_t)r0g * 1024 + col) = hi;
        *(uint32_t*)(c1 + (size_t)r0g * 1024 + col) = lo;
        split_pack(oacc[j][2] * inv1, oacc[j][3] * inv1, hi, lo);
        *(uint32_t*)(c0 + (size_t)r1g * 1024 + col) = hi;
        *(uint32_t*)(c1 + (size_t)r1g * 1024 + col) = lo;
    }
}

// ---------------- launch -----------------------------------------------------
extern "C" void kernel_launch(void* const* d_in, const int* in_sizes, int n_in,
                              void* d_out, int out_size)
{
    const float* x          = (const float*)d_in[0];
    const float* w_qkv      = (const float*)d_in[1];
    const float* b_qkv      = (const float*)d_in[2];
    const float* w_proj     = (const float*)d_in[3];
    const float* b_proj     = (const float*)d_in[4];
    const float* bias_table = (const float*)d_in[5];
    float* out = (float*)d_out;
    (void)in_sizes; (void)n_in; (void)out_size;

    cudaFuncSetAttribute(mma_gemm, cudaFuncAttributeMaxDynamicSharedMemorySize, GEMM_SMEM_BYTES);
    cudaFuncSetAttribute(attn_mma, cudaFuncAttributeMaxDynamicSharedMemorySize, ATTN_SMEM_BYTES);

    __nv_bfloat16 *qkv0, *qkv1, *x0, *x1, *wq0, *wq1, *wp0, *wp1, *c0, *c1;
    cudaGetSymbolAddress((void**)&qkv0, g_qkv0);  cudaGetSymbolAddress((void**)&qkv1, g_qkv1);
    cudaGetSymbolAddress((void**)&x0, g_x0);      cudaGetSymbolAddress((void**)&x1, g_x1);
    cudaGetSymbolAddress((void**)&wq0, g_wqkv0);  cudaGetSymbolAddress((void**)&wq1, g_wqkv1);
    cudaGetSymbolAddress((void**)&wp0, g_wp0);    cudaGetSymbolAddress((void**)&wp1, g_wp1);
    cudaGetSymbolAddress((void**)&c0, g_c0);      cudaGetSymbolAddress((void**)&c1, g_c1);

    // split inputs/weights into bf16 hi/lo planes (single merged launch)
    split_all<<<5120, 256>>>(x, w_qkv, w_proj, x0, x1, wq0, wq1, wp0, wp1);

    // 1) QKV projection -> bf16 planes (BM=64: grid y = 1024/64 = 16)
    mma_gemm<<<dim3(24, 16), 256, GEMM_SMEM_BYTES>>>(
        x0, x1, wq0, wq1, b_qkv, nullptr, qkv0, qkv1, 3072, 1024);

    // 2) tensor-core flash attention -> ctx bf16 planes
    attn_mma<<<dim3(8, 16), 256, ATTN_SMEM_BYTES>>>(qkv0, qkv1, bias_table, c0, c1);

    // 3) output projection -> fp32 out (grid (8, 16))
    mma_gemm<<<dim3(8, 16), 256, GEMM_SMEM_BYTES>>>(
        c0, c1, wp0, wp1, b_proj, out, nullptr, nullptr, 1024, 1024);
}

// round 9
// speedup vs baseline: 3.9865x; 1.1166x over previous
#include <cuda_runtime.h>
#include <cuda_bf16.h>
#include <cstdint>

// ---------------- scratch (device globals; no allocations allowed) ----------
__device__ __nv_bfloat16 g_qkv0[1024 * 3072], g_qkv1[1024 * 3072]; // qkv planes
__device__ __nv_bfloat16 g_x0[1024 * 1024],    g_x1[1024 * 1024];
__device__ __nv_bfloat16 g_wqkv0[3072 * 1024], g_wqkv1[3072 * 1024];
__device__ __nv_bfloat16 g_wp0[1024 * 1024],   g_wp1[1024 * 1024];
__device__ __nv_bfloat16 g_c0[1024 * 1024],    g_c1[1024 * 1024];  // ctx planes

// ---------------- helpers ----------------------------------------------------
__device__ __forceinline__ uint32_t smem_u32(const void* p) {
    uint32_t a;
    asm("{ .reg .u64 t; cvta.to.shared.u64 t, %1; cvt.u32.u64 %0, t; }" : "=r"(a) : "l"(p));
    return a;
}
#define SMEM_SWIZZLE_128B(b) ((b) ^ (((b) >> 3) & 0x70))

__device__ __forceinline__ void cp_async16(uint32_t dst, const void* src) {
    asm volatile("cp.async.cg.shared.global [%0], [%1], 16;" :: "r"(dst), "l"(src) : "memory");
}
__device__ __forceinline__ void ldsm4(uint32_t& r0, uint32_t& r1, uint32_t& r2,
                                      uint32_t& r3, uint32_t addr) {
    asm volatile("ldmatrix.sync.aligned.m8n8.x4.shared.b16 {%0,%1,%2,%3}, [%4];"
                 : "=r"(r0), "=r"(r1), "=r"(r2), "=r"(r3) : "r"(addr));
}
__device__ __forceinline__ void ldsm4t(uint32_t& r0, uint32_t& r1, uint32_t& r2,
                                       uint32_t& r3, uint32_t addr) {
    asm volatile("ldmatrix.sync.aligned.m8n8.x4.trans.shared.b16 {%0,%1,%2,%3}, [%4];"
                 : "=r"(r0), "=r"(r1), "=r"(r2), "=r"(r3) : "r"(addr));
}
__device__ __forceinline__ void mma16816(float* d, const uint32_t* a, const uint32_t* b) {
    asm volatile(
        "mma.sync.aligned.m16n8k16.row.col.f32.bf16.bf16.f32 "
        "{%0,%1,%2,%3}, {%4,%5,%6,%7}, {%8,%9}, {%0,%1,%2,%3};"
        : "+f"(d[0]), "+f"(d[1]), "+f"(d[2]), "+f"(d[3])
        : "r"(a[0]), "r"(a[1]), "r"(a[2]), "r"(a[3]), "r"(b[0]), "r"(b[1]));
}
__device__ __forceinline__ void split_pack(float a, float b, uint32_t& hi, uint32_t& lo) {
    __nv_bfloat162 h, l;
    h.x = __float2bfloat16_rn(a);
    h.y = __float2bfloat16_rn(b);
    l.x = __float2bfloat16_rn(a - __bfloat162float(h.x));
    l.y = __float2bfloat16_rn(b - __bfloat162float(h.y));
    hi = *(uint32_t*)&h;
    lo = *(uint32_t*)&l;
}

// ---------------- merged split fp32 -> (bf16 hi, bf16 lo) --------------------
__global__ __launch_bounds__(256) void split_all(
    const float* __restrict__ x, const float* __restrict__ wq,
    const float* __restrict__ wp,
    __nv_bfloat16* __restrict__ x0, __nv_bfloat16* __restrict__ x1,
    __nv_bfloat16* __restrict__ q0, __nv_bfloat16* __restrict__ q1,
    __nv_bfloat16* __restrict__ p0, __nv_bfloat16* __restrict__ p1)
{
    int b = blockIdx.x;
    const float* src;
    __nv_bfloat16 *d0, *d1;
    int base;
    if (b < 1024)      { src = x;  d0 = x0; d1 = x1; base = b; }
    else if (b < 4096) { src = wq; d0 = q0; d1 = q1; base = b - 1024; }
    else               { src = wp; d0 = p0; d1 = p1; base = b - 4096; }
    int i = base * 1024 + threadIdx.x * 4;
    float4 v = *(const float4*)(src + i);
    float vv[4] = {v.x, v.y, v.z, v.w};
    __nv_bfloat16 h0[4], h1[4];
#pragma unroll
    for (int j = 0; j < 4; j++) {
        h0[j] = __float2bfloat16_rn(vv[j]);
        h1[j] = __float2bfloat16_rn(vv[j] - __bfloat162float(h0[j]));
    }
    *(uint2*)(d0 + i) = *(const uint2*)h0;
    *(uint2*)(d1 + i) = *(const uint2*)h1;
}

// ---------------- mma.sync GEMM: C = A@B^T + bias, bf16 split-2 -------------
// BM=64, BN template (128 or 64), K-chunk 64, double-buffered smem.
// Buffer: [A0 8KB][A1 8KB][B0 BN*128][B1 BN*128]; 128-byte rows, SW128 swizzle.
// 8 warps: wm = wid&3 (16-row group), wn = wid>>2 (0..1, (BN/2)-col group).
template <int BN>
__global__ __launch_bounds__(256, 2) void mma_gemm(
    const __nv_bfloat16* __restrict__ A0, const __nv_bfloat16* __restrict__ A1,
    const __nv_bfloat16* __restrict__ B0, const __nv_bfloat16* __restrict__ B1,
    const float* __restrict__ bias, float* __restrict__ C,
    __nv_bfloat16* __restrict__ P0, __nv_bfloat16* __restrict__ P1, int N, int K)
{
    constexpr int NG    = BN / 32;              // 16-col groups per warp (4 or 2)
    constexpr int BPLNB = BN * 128;             // B plane bytes
    constexpr int BUFB  = 16384 + 2 * BPLNB;    // bytes per k-chunk buffer

    extern __shared__ char smem[];
    const uint32_t sb = smem_u32(smem);
    const int tid  = threadIdx.x;
    const int lane = tid & 31;
    const int wid  = tid >> 5;
    const int wm   = wid & 3;
    const int wn   = wid >> 2;
    const int bm = blockIdx.y, bn = blockIdx.x;

    const __nv_bfloat16* pa0 = A0 + (size_t)bm * 64 * K;
    const __nv_bfloat16* pa1 = A1 + (size_t)bm * 64 * K;
    const __nv_bfloat16* pb0 = B0 + (size_t)bn * BN * K;
    const __nv_bfloat16* pb1 = B1 + (size_t)bn * BN * K;

    float acc[2 * NG][4];
#pragma unroll
    for (int i = 0; i < 2 * NG; i++)
#pragma unroll
        for (int q = 0; q < 4; q++) acc[i][q] = 0.0f;

    const int NCH = K / 64;

    auto load_chunk = [&](int c) {
        const uint32_t bb = sb + (uint32_t)(c & 1) * BUFB;
        const int k0 = c * 64;
        // A planes: 1024 cp16 (2 planes x 64 rows x 8 segs)
#pragma unroll
        for (int i = 0; i < 4; i++) {
            int idx = i * 256 + tid;
            int pl = idx >> 9, w = idx & 511;
            int row = w >> 3, seg = w & 7;
            cp_async16(bb + pl * 8192
                           + SMEM_SWIZZLE_128B((uint32_t)(row * 128 + seg * 16)),
                       (pl ? pa1 : pa0) + (size_t)row * K + k0 + seg * 8);
        }
        // B planes: 2*BN*8 cp16
#pragma unroll
        for (int i = 0; i < BN / 16; i++) {
            int idx = i * 256 + tid;
            int pl = idx / (BN * 8), w = idx % (BN * 8);
            int row = w >> 3, seg = w & 7;
            cp_async16(bb + 16384 + pl * BPLNB
                           + SMEM_SWIZZLE_128B((uint32_t)(row * 128 + seg * 16)),
                       (pl ? pb1 : pb0) + (size_t)row * K + k0 + seg * 8);
        }
        asm volatile("cp.async.commit_group;" ::: "memory");
    };

    // ldmatrix lane address components (R6-verified)
    const int a_row  = lane & 15;
    const int a_kofs = (lane >> 4) * 8;
    const int b_row  = ((lane >> 4) << 3) + (lane & 7);
    const int b_kofs = lane & 8;

    load_chunk(0);

    for (int c = 0; c < NCH; c++) {
        if (c + 1 < NCH) {
            load_chunk(c + 1);   // safe: buf (c+1)&1 fully read before end of iter c-1
            asm volatile("cp.async.wait_group 1;" ::: "memory");
        } else {
            asm volatile("cp.async.wait_group 0;" ::: "memory");
        }
        __syncthreads();         // chunk c visible to all warps

        const uint32_t bb = sb + (uint32_t)(c & 1) * BUFB;
#pragma unroll
        for (int ks = 0; ks < 4; ks++) {
            uint32_t bf[2][NG][4];
#pragma unroll
            for (int pl = 0; pl < 2; pl++)
#pragma unroll
                for (int ng = 0; ng < NG; ng++) {
                    int row = wn * (NG * 16) + ng * 16 + b_row;
                    ldsm4(bf[pl][ng][0], bf[pl][ng][1], bf[pl][ng][2], bf[pl][ng][3],
                          bb + 16384 + pl * BPLNB + SMEM_SWIZZLE_128B(
                              (uint32_t)(row * 128 + (ks * 16 + b_kofs) * 2)));
                }
            uint32_t af0[4], af1[4];
            {
                uint32_t boff = SMEM_SWIZZLE_128B(
                    (uint32_t)((wm * 16 + a_row) * 128 + (ks * 16 + a_kofs) * 2));
                ldsm4(af0[0], af0[1], af0[2], af0[3], bb + boff);
                ldsm4(af1[0], af1[1], af1[2], af1[3], bb + 8192 + boff);
            }
#pragma unroll
            for (int ng = 0; ng < NG; ng++)
#pragma unroll
                for (int hf = 0; hf < 2; hf++) {
                    float* d = acc[ng * 2 + hf];
                    mma16816(d, af0, &bf[0][ng][hf * 2]);
                    mma16816(d, af0, &bf[1][ng][hf * 2]);
                    mma16816(d, af1, &bf[0][ng][hf * 2]);
                }
        }
        __syncthreads();         // all reads of buf c&1 done before reuse
    }

    // epilogue
    const int gr = bm * 64 + wm * 16 + (lane >> 2);
#pragma unroll
    for (int nt = 0; nt < 2 * NG; nt++) {
        int gc = bn * BN + wn * (NG * 16) + nt * 8 + (lane & 3) * 2;
        float b0 = bias[gc], b1 = bias[gc + 1];
        float v0 = acc[nt][0] + b0, v1 = acc[nt][1] + b1;
        float v2 = acc[nt][2] + b0, v3 = acc[nt][3] + b1;
        if (C) {
            *(float2*)(C + (size_t)gr * N + gc)       = make_float2(v0, v1);
            *(float2*)(C + (size_t)(gr + 8) * N + gc) = make_float2(v2, v3);
        } else {
            uint32_t hi, lo;
            split_pack(v0, v1, hi, lo);
            *(uint32_t*)(P0 + (size_t)gr * N + gc) = hi;
            *(uint32_t*)(P1 + (size_t)gr * N + gc) = lo;
            split_pack(v2, v3, hi, lo);
            *(uint32_t*)(P0 + (size_t)(gr + 8) * N + gc) = hi;
            *(uint32_t*)(P1 + (size_t)(gr + 8) * N + gc) = lo;
        }
    }
}

// ---------------- tensor-core flash attention (split-2 bf16) -----------------
// Grid (8 q-blocks of 128 rows, 16 heads), 256 threads = 8 warps.
#define ATTN_SMEM_BYTES (32768 + 65536 + 512)

__global__ __launch_bounds__(256, 1) void attn_mma(
    const __nv_bfloat16* __restrict__ qkv0, const __nv_bfloat16* __restrict__ qkv1,
    const float* __restrict__ bias_table,
    __nv_bfloat16* __restrict__ c0, __nv_bfloat16* __restrict__ c1)
{
    extern __shared__ char smem[];
    const uint32_t sb = smem_u32(smem);
    const uint32_t Q0 = sb, Q1 = sb + 16384;
    const uint32_t KV = sb + 32768;
    float* lut = (float*)(smem + 98304);

    const int tid  = threadIdx.x;
    const int lane = tid & 31;
    const int warp = tid >> 5;
    const int h    = blockIdx.y;
    const int qb   = blockIdx.x;
    const int q0r  = qb * 128;

    if (tid < 125) {
        int idx = min(63 * tid, 3968);
        lut[tid] = bias_table[idx * 16 + h];
    }

#pragma unroll
    for (int i = 0; i < 8; i++) {
        int idx = i * 256 + tid;
        int pl  = idx >> 10;
        int w   = idx & 1023;
        int row = w >> 3;
        int seg = w & 7;
        const __nv_bfloat16* src = (pl ? qkv1 : qkv0)
            + (size_t)(q0r + row) * 3072 + h * 64 + seg * 8;
        cp_async16((pl ? Q1 : Q0) + SMEM_SWIZZLE_128B((uint32_t)(row * 128 + seg * 16)), src);
    }

    auto load_kv = [&](int c) {
        const uint32_t bb = KV + (uint32_t)(c & 1) * 32768;
        const int m0 = c * 64;
#pragma unroll
        for (int i = 0; i < 8; i++) {
            int idx = i * 256 + tid;
            int tile = idx >> 9;
            int w    = idx & 511;
            int row  = w >> 3;
            int seg  = w & 7;
            const __nv_bfloat16* base = (tile & 1) ? qkv1 : qkv0;
            int off = (tile >> 1) ? 2048 : 1024;
            cp_async16(bb + tile * 8192 + SMEM_SWIZZLE_128B((uint32_t)(row * 128 + seg * 16)),
                       base + (size_t)(m0 + row) * 3072 + off + h * 64 + seg * 8);
        }
        asm volatile("cp.async.commit_group;" ::: "memory");
    };

    load_kv(0);

    const int a_row  = lane & 15;
    const int a_kofs = (lane >> 4) * 8;
    const int b_n    = ((lane >> 4) << 3) + (lane & 7);
    const int b_kofs = lane & 8;
    const int v_kv = ((lane >> 3) & 1) * 8 + (lane & 7);
    const int v_dh = (lane >> 4) * 8;

    const int r0g = q0r + warp * 16 + (lane >> 2);
    const int r1g = r0g + 8;
    const int qs0 = (r0g >> 5) + (r0g & 31);
    const int qs1 = (r1g >> 5) + (r1g & 31);

    uint32_t qa[2][4][4];
    float oacc[8][4];
#pragma unroll
    for (int j = 0; j < 8; j++)
#pragma unroll
        for (int q = 0; q < 4; q++) oacc[j][q] = 0.0f;
    float m0r = -1e30f, m1r = -1e30f, l0 = 0.0f, l1 = 0.0f;

    for (int c = 0; c < 16; c++) {
        if (c + 1 < 16) {
            load_kv(c + 1);
            asm volatile("cp.async.wait_group 1;" ::: "memory");
        } else {
            asm volatile("cp.async.wait_group 0;" ::: "memory");
        }
        __syncthreads();

        if (c == 0) {
#pragma unroll
            for (int pl = 0; pl < 2; pl++)
#pragma unroll
                for (int ks = 0; ks < 4; ks++) {
                    uint32_t boff = (uint32_t)((warp * 16 + a_row) * 128
                                               + (ks * 16 + a_kofs) * 2);
                    ldsm4(qa[pl][ks][0], qa[pl][ks][1], qa[pl][ks][2], qa[pl][ks][3],
                          (pl ? Q1 : Q0) + SMEM_SWIZZLE_128B(boff));
                }
        }

        const uint32_t bb = KV + (uint32_t)(c & 1) * 32768;

        float s[8][4];
#pragma unroll
        for (int j = 0; j < 8; j++)
#pragma unroll
            for (int q = 0; q < 4; q++) s[j][q] = 0.0f;

#pragma unroll
        for (int ks = 0; ks < 4; ks++)
#pragma unroll
            for (int ng = 0; ng < 4; ng++) {
                uint32_t boff = SMEM_SWIZZLE_128B(
                    (uint32_t)((ng * 16 + b_n) * 128 + (ks * 16 + b_kofs) * 2));
                uint32_t kb0[4], kb1[4];
                ldsm4(kb0[0], kb0[1], kb0[2], kb0[3], bb + boff);
                ldsm4(kb1[0], kb1[1], kb1[2], kb1[3], bb + 8192 + boff);
#pragma unroll
                for (int hf = 0; hf < 2; hf++) {
                    float* d = s[ng * 2 + hf];
                    mma16816(d, qa[0][ks], &kb0[hf * 2]);
                    mma16816(d, qa[0][ks], &kb1[hf * 2]);
                    mma16816(d, qa[1][ks], &kb0[hf * 2]);
                }
            }

        const int mbase = c * 64;
        float mx0 = -1e30f, mx1 = -1e30f;
#pragma unroll
        for (int j = 0; j < 8; j++) {
            int mc  = mbase + 8 * j + 2 * (lane & 3);
            int ms0 = (mc >> 5) + (mc & 31);
            int ms1 = ((mc + 1) >> 5) + ((mc + 1) & 31);
            s[j][0] = s[j][0] * 0.125f + lut[qs0 - ms0 + 62];
            s[j][1] = s[j][1] * 0.125f + lut[qs0 - ms1 + 62];
            s[j][2] = s[j][2] * 0.125f + lut[qs1 - ms0 + 62];
            s[j][3] = s[j][3] * 0.125f + lut[qs1 - ms1 + 62];
            mx0 = fmaxf(mx0, fmaxf(s[j][0], s[j][1]));
            mx1 = fmaxf(mx1, fmaxf(s[j][2], s[j][3]));
        }
        mx0 = fmaxf(mx0, __shfl_xor_sync(0xffffffffu, mx0, 1));
        mx0 = fmaxf(mx0, __shfl_xor_sync(0xffffffffu, mx0, 2));
        mx1 = fmaxf(mx1, __shfl_xor_sync(0xffffffffu, mx1, 1));
        mx1 = fmaxf(mx1, __shfl_xor_sync(0xffffffffu, mx1, 2));
        float nm0 = fmaxf(m0r, mx0), nm1 = fmaxf(m1r, mx1);
        float cr0 = __expf(m0r - nm0), cr1 = __expf(m1r - nm1);
        float ps0 = 0.0f, ps1 = 0.0f;
#pragma unroll
        for (int j = 0; j < 8; j++) {
            s[j][0] = __expf(s[j][0] - nm0);
            s[j][1] = __expf(s[j][1] - nm0);
            s[j][2] = __expf(s[j][2] - nm1);
            s[j][3] = __expf(s[j][3] - nm1);
            ps0 += s[j][0] + s[j][1];
            ps1 += s[j][2] + s[j][3];
        }
        ps0 += __shfl_xor_sync(0xffffffffu, ps0, 1);
        ps0 += __shfl_xor_sync(0xffffffffu, ps0, 2);
        ps1 += __shfl_xor_sync(0xffffffffu, ps1, 1);
        ps1 += __shfl_xor_sync(0xffffffffu, ps1, 2);
        l0 = l0 * cr0 + ps0;
        l1 = l1 * cr1 + ps1;
        m0r = nm0; m1r = nm1;
#pragma unroll
        for (int j = 0; j < 8; j++) {
            oacc[j][0] *= cr0; oacc[j][1] *= cr0;
            oacc[j][2] *= cr1; oacc[j][3] *= cr1;
        }

        uint32_t p0a[4][4], p1a[4][4];
#pragma unroll
        for (int ks = 0; ks < 4; ks++) {
            int j0 = 2 * ks, j1 = 2 * ks + 1;
            split_pack(s[j0][0], s[j0][1], p0a[ks][0], p1a[ks][0]);
            split_pack(s[j0][2], s[j0][3], p0a[ks][1], p1a[ks][1]);
            split_pack(s[j1][0], s[j1][1], p0a[ks][2], p1a[ks][2]);
            split_pack(s[j1][2], s[j1][3], p0a[ks][3], p1a[ks][3]);
        }

#pragma unroll
        for (int ks = 0; ks < 4; ks++)
#pragma unroll
            for (int dg = 0; dg < 4; dg++) {
                uint32_t boff = SMEM_SWIZZLE_128B(
                    (uint32_t)((ks * 16 + v_kv) * 128 + (dg * 16 + v_dh) * 2));
                uint32_t vb0[4], vb1[4];
                ldsm4t(vb0[0], vb0[1], vb0[2], vb0[3], bb + 16384 + boff);
                ldsm4t(vb1[0], vb1[1], vb1[2], vb1[3], bb + 24576 + boff);
#pragma unroll
                for (int hf = 0; hf < 2; hf++) {
                    float* d = oacc[dg * 2 + hf];
                    mma16816(d, p0a[ks], &vb0[hf * 2]);
                    mma16816(d, p0a[ks], &vb1[hf * 2]);
                    mma16816(d, p1a[ks], &vb0[hf * 2]);
                }
            }
        __syncthreads();
    }

    float inv0 = 1.0f / l0, inv1 = 1.0f / l1;
#pragma unroll
    for (int j = 0; j < 8; j++) {
        int col = h * 64 + 8 * j + 2 * (lane & 3);
        uint32_t hi, lo;
        split_pack(oacc[j][0] * inv0, oacc[j][1] * inv0, hi, lo);
        *(uint32_t*)(c0 + (size_t)r0g * 1024 + col) = hi;
        *(uint32_t*)(c1 + (size_t)r0g * 1024 + col) = lo;
        split_pack(oacc[j][2] * inv1, oacc[j][3] * inv1, hi, lo);
        *(uint32_t*)(c0 + (size_t)r1g * 1024 + col) = hi;
        *(uint32_t*)(c1 + (size_t)r1g * 1024 + col) = lo;
    }
}

// ---------------- launch -----------------------------------------------------
#define GEMM128_SMEM (2 * (16384 + 2 * 128 * 128))   // 98304
#define GEMM64_SMEM  (2 * (16384 + 2 * 64 * 128))    // 65536

extern "C" void kernel_launch(void* const* d_in, const int* in_sizes, int n_in,
                              void* d_out, int out_size)
{
    const float* x          = (const float*)d_in[0];
    const float* w_qkv      = (const float*)d_in[1];
    const float* b_qkv      = (const float*)d_in[2];
    const float* w_proj     = (const float*)d_in[3];
    const float* b_proj     = (const float*)d_in[4];
    const float* bias_table = (const float*)d_in[5];
    float* out = (float*)d_out;
    (void)in_sizes; (void)n_in; (void)out_size;

    cudaFuncSetAttribute(mma_gemm<128>, cudaFuncAttributeMaxDynamicSharedMemorySize, GEMM128_SMEM);
    cudaFuncSetAttribute(mma_gemm<64>,  cudaFuncAttributeMaxDynamicSharedMemorySize, GEMM64_SMEM);
    cudaFuncSetAttribute(attn_mma, cudaFuncAttributeMaxDynamicSharedMemorySize, ATTN_SMEM_BYTES);

    __nv_bfloat16 *qkv0, *qkv1, *x0, *x1, *wq0, *wq1, *wp0, *wp1, *c0, *c1;
    cudaGetSymbolAddress((void**)&qkv0, g_qkv0);  cudaGetSymbolAddress((void**)&qkv1, g_qkv1);
    cudaGetSymbolAddress((void**)&x0, g_x0);      cudaGetSymbolAddress((void**)&x1, g_x1);
    cudaGetSymbolAddress((void**)&wq0, g_wqkv0);  cudaGetSymbolAddress((void**)&wq1, g_wqkv1);
    cudaGetSymbolAddress((void**)&wp0, g_wp0);    cudaGetSymbolAddress((void**)&wp1, g_wp1);
    cudaGetSymbolAddress((void**)&c0, g_c0);      cudaGetSymbolAddress((void**)&c1, g_c1);

    // split inputs/weights into bf16 hi/lo planes (single merged launch)
    split_all<<<5120, 256>>>(x, w_qkv, w_proj, x0, x1, wq0, wq1, wp0, wp1);

    // 1) QKV projection -> bf16 planes (BN=128: grid 24x16 = 384 CTAs, 2/SM)
    mma_gemm<128><<<dim3(24, 16), 256, GEMM128_SMEM>>>(
        x0, x1, wq0, wq1, b_qkv, nullptr, qkv0, qkv1, 3072, 1024);

    // 2) tensor-core flash attention -> ctx bf16 planes
    attn_mma<<<dim3(8, 16), 256, ATTN_SMEM_BYTES>>>(qkv0, qkv1, bias_table, c0, c1);

    // 3) output projection -> fp32 out (BN=64: grid 16x16 = 256 CTAs, ~1.7/SM)
    mma_gemm<64><<<dim3(16, 16), 256, GEMM64_SMEM>>>(
        c0, c1, wp0, wp1, b_proj, out, nullptr, nullptr, 1024, 1024);
}